// round 1
// baseline (speedup 1.0000x reference)
#include <cuda_runtime.h>
#include <cuda_bf16.h>
#include <math.h>

// Problem constants
#define LN 12
#define BB 4
#define NN 512
#define SS 512
#define VV 32000
#define HH 768
#define NH 8
#define DH 96
#define MROWS (BB*NN)          // 2048
#define KVLEN (SS+NN)          // 1024

// ---------------- scratch (device globals; no allocation allowed) ----------
__device__ float g_hidden[MROWS*HH];
__device__ float g_x[MROWS*HH];
__device__ float g_qkv[MROWS*3*HH];
__device__ float g_q[MROWS*HH];
__device__ float g_kcat[BB*KVLEN*HH];
__device__ float g_vcat[BB*KVLEN*HH];
__device__ float g_attn[MROWS*HH];
__device__ float g_ffn[MROWS*HH];
__device__ float g_embedT[(long)HH*VV];

// ---------------- embed transpose: E[V,H] -> ET[H,V] ------------------------
__global__ void transpose_k(const float* __restrict__ E, float* __restrict__ ET) {
    __shared__ float tile[32][33];
    int bx = blockIdx.x, by = blockIdx.y;
    int tx = threadIdx.x, ty = threadIdx.y;
    #pragma unroll
    for (int j = 0; j < 32; j += 8)
        tile[ty + j][tx] = E[(long)(by*32 + ty + j)*HH + bx*32 + tx];
    __syncthreads();
    #pragma unroll
    for (int j = 0; j < 32; j += 8)
        ET[(long)(bx*32 + ty + j)*VV + by*32 + tx] = tile[tx][ty + j];
}

// ---------------- embedding gather + scale ----------------------------------
__global__ void embed_k(const int* __restrict__ ids, const float* __restrict__ E,
                        float* __restrict__ hid) {
    long idx = (long)blockIdx.x * blockDim.x + threadIdx.x;
    if (idx >= (long)MROWS*HH) return;
    int col = (int)(idx % HH);
    long row = idx / HH;
    hid[idx] = E[(long)ids[row]*HH + col] * 27.712812921102035f; // sqrt(768)
}

// ---------------- RMSNorm (GemmaRMSNorm) ------------------------------------
__global__ __launch_bounds__(256) void rmsnorm_k(const float* __restrict__ x,
                                                 const float* __restrict__ w,
                                                 float* __restrict__ y) {
    int row = blockIdx.x;
    const float* xr = x + (long)row*HH;
    float s = 0.f;
    for (int c = threadIdx.x; c < HH; c += 256) { float v = xr[c]; s += v*v; }
    __shared__ float red[8];
    #pragma unroll
    for (int o = 16; o; o >>= 1) s += __shfl_xor_sync(~0u, s, o);
    if ((threadIdx.x & 31) == 0) red[threadIdx.x >> 5] = s;
    __syncthreads();
    if (threadIdx.x < 8) {
        float t = red[threadIdx.x];
        #pragma unroll
        for (int o = 4; o; o >>= 1) t += __shfl_xor_sync(0xffu, t, o);
        if (threadIdx.x == 0) red[0] = t;
    }
    __syncthreads();
    float inv = rsqrtf(red[0] / (float)HH + 1e-6f);
    for (int c = threadIdx.x; c < HH; c += 256)
        y[(long)row*HH + c] = xr[c] * inv * (1.f + w[c]);
}

// ---------------- RoPE + q/k/v split-scatter --------------------------------
// qkv: [2048, 2304]. q -> g_q [b,n, h*96+d]; rope(k) -> kcat rows 512+n; v -> vcat.
__global__ void rope_split_k(const float* __restrict__ qkv, float* __restrict__ qb,
                             float* __restrict__ kcat, float* __restrict__ vcat) {
    long idx = (long)blockIdx.x * blockDim.x + threadIdx.x;
    if (idx >= (long)MROWS*HH) return;
    int col = (int)(idx % HH);
    long row = idx / HH;
    int n = (int)(row % NN);
    int b = (int)(row / NN);
    int dd = col % DH;
    const float* base = qkv + row*(3*HH);
    float qv = base[col], kv = base[HH + col], vv = base[2*HH + col];
    int t = (dd < DH/2) ? dd : dd - DH/2;
    double invf = pow(10000.0, -((double)(2*t) / (double)DH));
    double fd = (double)n * invf;
    float c = (float)cos(fd), s = (float)sin(fd);
    float qrot = (dd < DH/2) ? -base[col + DH/2]      : base[col - DH/2];
    float krot = (dd < DH/2) ? -base[HH + col + DH/2] : base[HH + col - DH/2];
    qb[row*HH + col] = qv*c + qrot*s;
    long outk = ((long)b*KVLEN + SS + n)*HH + col;
    kcat[outk] = kv*c + krot*s;
    vcat[outk] = vv;
}

// ---------------- generic fp32 SGEMM  C = A@W (+bias)(+res)(gelu) -----------
// A [M,P] row-major, W [P,K] row-major, C [M,K] (optionally segmented rows:
// out offset = (r/rowseg)*segstride + (r%rowseg)*K + c). M,K multiples of 128,
// P multiple of 8 (guaranteed by problem shapes).
__global__ __launch_bounds__(256) void sgemm_k(
    const float* __restrict__ A, const float* __restrict__ W,
    const float* __restrict__ bias, const float* res, float* C,
    int M, int P, int K, int act, int rowseg, long long segstride)
{
    __shared__ __align__(16) float As[8][128];
    __shared__ __align__(16) float Bs[8][128];
    const int tid = threadIdx.x;
    const int tx = tid & 15, ty = tid >> 4;
    const int row0 = blockIdx.y * 128;
    const int col0 = blockIdx.x * 128;

    float acc[8][8];
    #pragma unroll
    for (int i = 0; i < 8; i++)
        #pragma unroll
        for (int j = 0; j < 8; j++) acc[i][j] = 0.f;

    const int ar = tid >> 1, apq = tid & 1;       // A-load: row, float4 index
    const int bp = tid >> 5, bc4 = tid & 31;      // B-load: p, float4 col

    for (int p0 = 0; p0 < P; p0 += 8) {
        float4 va = *(const float4*)(A + (long)(row0 + ar)*P + p0 + apq*4);
        As[apq*4 + 0][ar] = va.x;
        As[apq*4 + 1][ar] = va.y;
        As[apq*4 + 2][ar] = va.z;
        As[apq*4 + 3][ar] = va.w;
        float4 vb = *(const float4*)(W + (long)(p0 + bp)*K + col0 + bc4*4);
        *(float4*)&Bs[bp][bc4*4] = vb;
        __syncthreads();
        #pragma unroll
        for (int p = 0; p < 8; p++) {
            float4 a0 = *(float4*)&As[p][ty*4];
            float4 a1 = *(float4*)&As[p][64 + ty*4];
            float4 b0 = *(float4*)&Bs[p][tx*4];
            float4 b1 = *(float4*)&Bs[p][64 + tx*4];
            float av[8] = {a0.x, a0.y, a0.z, a0.w, a1.x, a1.y, a1.z, a1.w};
            float bv[8] = {b0.x, b0.y, b0.z, b0.w, b1.x, b1.y, b1.z, b1.w};
            #pragma unroll
            for (int i = 0; i < 8; i++)
                #pragma unroll
                for (int j = 0; j < 8; j++) acc[i][j] += av[i] * bv[j];
        }
        __syncthreads();
    }

    int rr[8], cc[8];
    #pragma unroll
    for (int i = 0; i < 4; i++) {
        rr[i]     = row0 + ty*4 + i;
        rr[i + 4] = row0 + 64 + ty*4 + i;
        cc[i]     = col0 + tx*4 + i;
        cc[i + 4] = col0 + 64 + tx*4 + i;
    }
    #pragma unroll
    for (int i = 0; i < 8; i++) {
        long obase = (long)(rr[i] / rowseg) * segstride + (long)(rr[i] % rowseg) * K;
        #pragma unroll
        for (int j = 0; j < 8; j++) {
            float v = acc[i][j];
            if (bias) v += bias[cc[j]];
            if (res)  v += res[(long)rr[i]*K + cc[j]];
            if (act == 1) v = 0.5f * v * (1.f + erff(v * 0.70710678118654752f));
            C[obase + cc[j]] = v;
        }
    }
}

// ---------------- attention: one block per (b, h, query i) ------------------
__global__ __launch_bounds__(128) void attn_k(
    const float* __restrict__ q, const float* __restrict__ kcat,
    const float* __restrict__ vcat, float* __restrict__ out)
{
    const int i = blockIdx.x, h = blockIdx.y, b = blockIdx.z;
    const int tid = threadIdx.x, lane = tid & 31, w = tid >> 5;
    __shared__ float qs[DH];
    __shared__ float sc[KVLEN];
    __shared__ float redm[4], reds[4];
    __shared__ float outs[4][DH];

    const float* qp = q + ((long)b*NN + i)*HH + h*DH;
    if (tid < DH) qs[tid] = qp[tid];
    __syncthreads();

    const int jmax = SS + i + 1;
    const float scale = rsqrtf((float)DH);
    const float* kb = kcat + (long)b*KVLEN*HH + h*DH;

    for (int j = w; j < KVLEN; j += 4) {
        float d = -3.0e38f;
        if (j < jmax) {
            const float* kr = kb + (long)j*HH;
            d = qs[lane]*kr[lane] + qs[lane+32]*kr[lane+32] + qs[lane+64]*kr[lane+64];
            #pragma unroll
            for (int o = 16; o; o >>= 1) d += __shfl_xor_sync(~0u, d, o);
            d *= scale;
        }
        if (lane == 0) sc[j] = d;
    }
    __syncthreads();

    float m = -3.0e38f;
    for (int j = tid; j < KVLEN; j += 128) m = fmaxf(m, sc[j]);
    #pragma unroll
    for (int o = 16; o; o >>= 1) m = fmaxf(m, __shfl_xor_sync(~0u, m, o));
    if (lane == 0) redm[w] = m;
    __syncthreads();
    const float bm = fmaxf(fmaxf(redm[0], redm[1]), fmaxf(redm[2], redm[3]));

    float s = 0.f;
    for (int j = tid; j < KVLEN; j += 128) {
        float e = (j < jmax) ? expf(sc[j] - bm) : 0.f;
        sc[j] = e;
        s += e;
    }
    #pragma unroll
    for (int o = 16; o; o >>= 1) s += __shfl_xor_sync(~0u, s, o);
    if (lane == 0) reds[w] = s;
    __syncthreads();
    const float inv = 1.f / (reds[0] + reds[1] + reds[2] + reds[3]);

    float a0 = 0.f, a1 = 0.f, a2 = 0.f;
    const float* vb = vcat + (long)b*KVLEN*HH + h*DH;
    for (int j = w; j < jmax; j += 4) {
        float p = sc[j];
        const float* vr = vb + (long)j*HH;
        a0 += p * vr[lane];
        a1 += p * vr[lane + 32];
        a2 += p * vr[lane + 64];
    }
    outs[w][lane] = a0; outs[w][lane + 32] = a1; outs[w][lane + 64] = a2;
    __syncthreads();
    if (tid < DH) {
        float v = (outs[0][tid] + outs[1][tid] + outs[2][tid] + outs[3][tid]) * inv;
        out[((long)b*NN + i)*HH + h*DH + tid] = v;
    }
}

// ---------------- host launcher ---------------------------------------------
static void sgemm(const float* A, const float* W, const float* bias,
                  const float* res, float* C, int M, int P, int K,
                  int act, int rowseg, long long segstride) {
    dim3 grid(K / 128, M / 128);
    sgemm_k<<<grid, 256>>>(A, W, bias, res, C, M, P, K, act, rowseg, segstride);
}

extern "C" void kernel_launch(void* const* d_in, const int* in_sizes, int n_in,
                              void* d_out, int out_size) {
    const int*   ids    = (const int*)  d_in[0];
    const float* vkey   = (const float*)d_in[1];   // [L,B,S,H]
    const float* vval   = (const float*)d_in[2];
    const float* embedW = (const float*)d_in[3];   // [V,H]
    const float* n1w    = (const float*)d_in[4];
    const float* n2w    = (const float*)d_in[5];
    const float* qkvW   = (const float*)d_in[6];   // [L,H,3H]
    const float* qkvB   = (const float*)d_in[7];
    const float* skvW   = (const float*)d_in[8];   // [L,H,H]
    const float* skvB   = (const float*)d_in[9];
    const float* outW   = (const float*)d_in[10];
    const float* outB   = (const float*)d_in[11];
    const float* f1W    = (const float*)d_in[12];
    const float* f1B    = (const float*)d_in[13];
    const float* f2W    = (const float*)d_in[14];
    const float* f2B    = (const float*)d_in[15];
    float* logits = (float*)d_out;

    float *hid, *x, *qkv, *q, *kc, *vc, *attn, *ffn, *eT;
    cudaGetSymbolAddress((void**)&hid,  g_hidden);
    cudaGetSymbolAddress((void**)&x,    g_x);
    cudaGetSymbolAddress((void**)&qkv,  g_qkv);
    cudaGetSymbolAddress((void**)&q,    g_q);
    cudaGetSymbolAddress((void**)&kc,   g_kcat);
    cudaGetSymbolAddress((void**)&vc,   g_vcat);
    cudaGetSymbolAddress((void**)&attn, g_attn);
    cudaGetSymbolAddress((void**)&ffn,  g_ffn);
    cudaGetSymbolAddress((void**)&eT,   g_embedT);

    // lm_head weight transpose (done every call; deterministic)
    transpose_k<<<dim3(HH/32, VV/32), dim3(32, 8)>>>(embedW, eT);

    const int elemBlocks = (MROWS*HH + 255) / 256;
    embed_k<<<elemBlocks, 256>>>(ids, embedW, hid);

    const long HW  = (long)HH * HH;       // 589824
    const long BSH = (long)BB * SS * HH;  // per-layer vlm slice

    for (int l = 0; l < LN; l++) {
        rmsnorm_k<<<MROWS, 256>>>(hid, n1w + l*HH, x);
        sgemm(x, qkvW + (long)l*HH*3*HH, qkvB + l*3*HH, nullptr, qkv,
              MROWS, HH, 3*HH, 0, MROWS, 0);
        rope_split_k<<<elemBlocks, 256>>>(qkv, q, kc, vc);
        // state keys/values: GEMM writes straight into kcat/vcat rows [0,512)
        sgemm(vkey + (long)l*BSH, skvW + l*HW, skvB + l*HH, nullptr, kc,
              MROWS, HH, HH, 0, SS, (long long)KVLEN*HH);
        sgemm(vval + (long)l*BSH, skvW + l*HW, skvB + l*HH, nullptr, vc,
              MROWS, HH, HH, 0, SS, (long long)KVLEN*HH);
        attn_k<<<dim3(NN, NH, BB), 128>>>(q, kc, vc, attn);
        sgemm(attn, outW + l*HW, outB + l*HH, hid, hid,
              MROWS, HH, HH, 0, MROWS, 0);
        rmsnorm_k<<<MROWS, 256>>>(hid, n2w + l*HH, x);
        sgemm(x, f1W + l*HW, f1B + l*HH, nullptr, ffn,
              MROWS, HH, HH, 1 /*gelu*/, MROWS, 0);
        sgemm(ffn, f2W + l*HW, f2B + l*HH, hid, hid,
              MROWS, HH, HH, 0, MROWS, 0);
    }

    // tied lm_head: logits = hidden @ embed^T
    sgemm(hid, eT, nullptr, nullptr, logits, MROWS, HH, VV, 0, MROWS, 0);
}

// round 2
// speedup vs baseline: 1.8278x; 1.8278x over previous
#include <cuda_runtime.h>
#include <cuda_bf16.h>
#include <math.h>

// Problem constants
#define LN 12
#define BB 4
#define NN 512
#define SS 512
#define VV 32000
#define HH 768
#define NH 8
#define DH 96
#define MROWS (BB*NN)          // 2048
#define KVLEN (SS+NN)          // 1024

// ---------------- scratch (device globals; no allocation allowed) ----------
__device__ float g_hidden[MROWS*HH];
__device__ float g_x[MROWS*HH];
__device__ float g_qkv[MROWS*3*HH];
__device__ float g_q[MROWS*HH];
__device__ float g_kcat[BB*KVLEN*HH];
__device__ float g_vcat[BB*KVLEN*HH];
__device__ float g_attn[MROWS*HH];
__device__ float g_ffn[MROWS*HH];
__device__ float g_embedT[(long)HH*VV];
__device__ float g_cos[NN*DH];
__device__ float g_sin[NN*DH];

// ---------------- embed transpose: E[V,H] -> ET[H,V] ------------------------
__global__ void transpose_k(const float* __restrict__ E, float* __restrict__ ET) {
    __shared__ float tile[32][33];
    int bx = blockIdx.x, by = blockIdx.y;
    int tx = threadIdx.x, ty = threadIdx.y;
    #pragma unroll
    for (int j = 0; j < 32; j += 8)
        tile[ty + j][tx] = E[(long)(by*32 + ty + j)*HH + bx*32 + tx];
    __syncthreads();
    #pragma unroll
    for (int j = 0; j < 32; j += 8)
        ET[(long)(bx*32 + ty + j)*VV + by*32 + tx] = tile[tx][ty + j];
}

// ---------------- embedding gather + scale ----------------------------------
__global__ void embed_k(const int* __restrict__ ids, const float* __restrict__ E,
                        float* __restrict__ hid) {
    long idx = (long)blockIdx.x * blockDim.x + threadIdx.x;
    if (idx >= (long)MROWS*HH) return;
    int col = (int)(idx % HH);
    long row = idx / HH;
    hid[idx] = E[(long)ids[row]*HH + col] * 27.712812921102035f; // sqrt(768)
}

// ---------------- RMSNorm (GemmaRMSNorm) ------------------------------------
__global__ __launch_bounds__(256) void rmsnorm_k(const float* __restrict__ x,
                                                 const float* __restrict__ w,
                                                 float* __restrict__ y) {
    int row = blockIdx.x;
    const float* xr = x + (long)row*HH;
    float s = 0.f;
    for (int c = threadIdx.x; c < HH; c += 256) { float v = xr[c]; s += v*v; }
    __shared__ float red[8];
    #pragma unroll
    for (int o = 16; o; o >>= 1) s += __shfl_xor_sync(~0u, s, o);
    if ((threadIdx.x & 31) == 0) red[threadIdx.x >> 5] = s;
    __syncthreads();
    if (threadIdx.x < 8) {
        float t = red[threadIdx.x];
        #pragma unroll
        for (int o = 4; o; o >>= 1) t += __shfl_xor_sync(0xffu, t, o);
        if (threadIdx.x == 0) red[0] = t;
    }
    __syncthreads();
    float inv = rsqrtf(red[0] / (float)HH + 1e-6f);
    for (int c = threadIdx.x; c < HH; c += 256)
        y[(long)row*HH + c] = xr[c] * inv * (1.f + w[c]);
}

// ---------------- RoPE cos/sin table (once per call, fp32) ------------------
__global__ void rope_tab_k(float* __restrict__ ct, float* __restrict__ st) {
    int idx = blockIdx.x * blockDim.x + threadIdx.x;
    if (idx >= NN*DH) return;
    int n = idx / DH, dd = idx % DH;
    int t = (dd < DH/2) ? dd : dd - DH/2;
    float invf = __powf(10000.f, -((float)(2*t) / (float)DH));
    float fd = (float)n * invf;
    ct[idx] = cosf(fd);
    st[idx] = sinf(fd);
}

// ---------------- RoPE + q/k/v split-scatter --------------------------------
__global__ void rope_split_k(const float* __restrict__ qkv, float* __restrict__ qb,
                             float* __restrict__ kcat, float* __restrict__ vcat,
                             const float* __restrict__ ct, const float* __restrict__ st) {
    long idx = (long)blockIdx.x * blockDim.x + threadIdx.x;
    if (idx >= (long)MROWS*HH) return;
    int col = (int)(idx % HH);
    long row = idx / HH;
    int n = (int)(row % NN);
    int b = (int)(row / NN);
    int dd = col % DH;
    const float* base = qkv + row*(3*HH);
    float qv = base[col], kv = base[HH + col], vv = base[2*HH + col];
    float c = ct[n*DH + dd], s = st[n*DH + dd];
    float qrot = (dd < DH/2) ? -base[col + DH/2]      : base[col - DH/2];
    float krot = (dd < DH/2) ? -base[HH + col + DH/2] : base[HH + col - DH/2];
    qb[row*HH + col] = qv*c + qrot*s;
    long outk = ((long)b*KVLEN + SS + n)*HH + col;
    kcat[outk] = kv*c + krot*s;
    vcat[outk] = vv;
}

// ---------------- generic fp32 SGEMM  C = A@W (+bias)(+res)(gelu) -----------
__global__ __launch_bounds__(256) void sgemm_k(
    const float* __restrict__ A, const float* __restrict__ W,
    const float* __restrict__ bias, const float* res, float* C,
    int M, int P, int K, int act, int rowseg, long long segstride)
{
    __shared__ __align__(16) float As[8][128];
    __shared__ __align__(16) float Bs[8][128];
    const int tid = threadIdx.x;
    const int tx = tid & 15, ty = tid >> 4;
    const int row0 = blockIdx.y * 128;
    const int col0 = blockIdx.x * 128;

    float acc[8][8];
    #pragma unroll
    for (int i = 0; i < 8; i++)
        #pragma unroll
        for (int j = 0; j < 8; j++) acc[i][j] = 0.f;

    const int ar = tid >> 1, apq = tid & 1;
    const int bp = tid >> 5, bc4 = tid & 31;

    for (int p0 = 0; p0 < P; p0 += 8) {
        float4 va = *(const float4*)(A + (long)(row0 + ar)*P + p0 + apq*4);
        As[apq*4 + 0][ar] = va.x;
        As[apq*4 + 1][ar] = va.y;
        As[apq*4 + 2][ar] = va.z;
        As[apq*4 + 3][ar] = va.w;
        float4 vb = *(const float4*)(W + (long)(p0 + bp)*K + col0 + bc4*4);
        *(float4*)&Bs[bp][bc4*4] = vb;
        __syncthreads();
        #pragma unroll
        for (int p = 0; p < 8; p++) {
            float4 a0 = *(float4*)&As[p][ty*4];
            float4 a1 = *(float4*)&As[p][64 + ty*4];
            float4 b0 = *(float4*)&Bs[p][tx*4];
            float4 b1 = *(float4*)&Bs[p][64 + tx*4];
            float av[8] = {a0.x, a0.y, a0.z, a0.w, a1.x, a1.y, a1.z, a1.w};
            float bv[8] = {b0.x, b0.y, b0.z, b0.w, b1.x, b1.y, b1.z, b1.w};
            #pragma unroll
            for (int i = 0; i < 8; i++)
                #pragma unroll
                for (int j = 0; j < 8; j++) acc[i][j] += av[i] * bv[j];
        }
        __syncthreads();
    }

    int rr[8], cc[8];
    #pragma unroll
    for (int i = 0; i < 4; i++) {
        rr[i]     = row0 + ty*4 + i;
        rr[i + 4] = row0 + 64 + ty*4 + i;
        cc[i]     = col0 + tx*4 + i;
        cc[i + 4] = col0 + 64 + tx*4 + i;
    }
    #pragma unroll
    for (int i = 0; i < 8; i++) {
        long obase = (long)(rr[i] / rowseg) * segstride + (long)(rr[i] % rowseg) * K;
        #pragma unroll
        for (int j = 0; j < 8; j++) {
            float v = acc[i][j];
            if (bias) v += bias[cc[j]];
            if (res)  v += res[(long)rr[i]*K + cc[j]];
            if (act == 1) v = 0.5f * v * (1.f + erff(v * 0.70710678118654752f));
            C[obase + cc[j]] = v;
        }
    }
}

// ---------------- flash-style attention: 64q x 64kv tiles -------------------
// Grid: (NN/64, NH, BB), 256 threads (tx 0..15, ty 0..15).
// Smem (dynamic): Qs[96][68] k-major, Ks[96][68] k-major, Vs[64][100], Ps[64][68].
#define QS_OFF 0
#define KS_OFF (96*68)
#define VS_OFF (2*96*68)
#define PS_OFF (2*96*68 + 64*100)
#define ATTN_SMEM ((2*96*68 + 64*100 + 64*68) * 4)

__global__ __launch_bounds__(256) void attn2_k(
    const float* __restrict__ q, const float* __restrict__ kcat,
    const float* __restrict__ vcat, float* __restrict__ out)
{
    extern __shared__ float sm[];
    float* Qs = sm + QS_OFF;
    float* Ks = sm + KS_OFF;
    float* Vs = sm + VS_OFF;
    float* Ps = sm + PS_OFF;

    const int qt = blockIdx.x, h = blockIdx.y, b = blockIdx.z;
    const int tid = threadIdx.x, tx = tid & 15, ty = tid >> 4;

    // load Q tile transposed (k-major)
    const float* qbase = q + ((long)b*NN + qt*64)*HH + h*DH;
    for (int c = tid; c < 64*24; c += 256) {
        int row = c / 24, k4 = (c % 24) * 4;
        float4 v = *(const float4*)(qbase + (long)row*HH + k4);
        Qs[(k4+0)*68 + row] = v.x;
        Qs[(k4+1)*68 + row] = v.y;
        Qs[(k4+2)*68 + row] = v.z;
        Qs[(k4+3)*68 + row] = v.w;
    }

    float m[4], l[4], o[4][6];
    #pragma unroll
    for (int i = 0; i < 4; i++) {
        m[i] = -3.0e38f; l[i] = 0.f;
        #pragma unroll
        for (int c = 0; c < 6; c++) o[i][c] = 0.f;
    }

    const float scale = 0.10206207261596575f; // 96^-0.5
    const int ntiles = SS/64 + qt + 1;        // 9 + qt
    const float* kb = kcat + (long)b*KVLEN*HH + h*DH;
    const float* vb = vcat + (long)b*KVLEN*HH + h*DH;

    for (int t = 0; t < ntiles; t++) {
        __syncthreads();  // previous-iteration consumers done before overwrite
        for (int c = tid; c < 64*24; c += 256) {
            int row = c / 24, k4 = (c % 24) * 4;
            float4 kv = *(const float4*)(kb + (long)(t*64 + row)*HH + k4);
            Ks[(k4+0)*68 + row] = kv.x;
            Ks[(k4+1)*68 + row] = kv.y;
            Ks[(k4+2)*68 + row] = kv.z;
            Ks[(k4+3)*68 + row] = kv.w;
            float4 vv = *(const float4*)(vb + (long)(t*64 + row)*HH + k4);
            *(float4*)&Vs[row*100 + k4] = vv;
        }
        __syncthreads();

        // S = Q @ K^T  (4x4 per thread)
        float s[4][4];
        #pragma unroll
        for (int i = 0; i < 4; i++)
            #pragma unroll
            for (int j = 0; j < 4; j++) s[i][j] = 0.f;

        #pragma unroll 4
        for (int k = 0; k < DH; k++) {
            float4 qa = *(float4*)&Qs[k*68 + ty*4];
            float4 ka = *(float4*)&Ks[k*68 + tx*4];
            float av[4] = {qa.x, qa.y, qa.z, qa.w};
            float bv[4] = {ka.x, ka.y, ka.z, ka.w};
            #pragma unroll
            for (int i = 0; i < 4; i++)
                #pragma unroll
                for (int j = 0; j < 4; j++) s[i][j] += av[i] * bv[j];
        }

        const bool last = (t == ntiles - 1);
        #pragma unroll
        for (int i = 0; i < 4; i++) {
            #pragma unroll
            for (int j = 0; j < 4; j++) {
                float v = s[i][j] * scale;
                if (last && (tx*4 + j) > (ty*4 + i)) v = -1.0e30f;
                s[i][j] = v;
            }
        }

        // online softmax update (row reductions across the 16 tx lanes)
        #pragma unroll
        for (int i = 0; i < 4; i++) {
            float cm = fmaxf(fmaxf(s[i][0], s[i][1]), fmaxf(s[i][2], s[i][3]));
            #pragma unroll
            for (int off = 1; off < 16; off <<= 1)
                cm = fmaxf(cm, __shfl_xor_sync(0xffffffffu, cm, off));
            float mn = fmaxf(m[i], cm);
            float fac = __expf(m[i] - mn);
            float p0 = __expf(s[i][0] - mn);
            float p1 = __expf(s[i][1] - mn);
            float p2 = __expf(s[i][2] - mn);
            float p3 = __expf(s[i][3] - mn);
            float rs = p0 + p1 + p2 + p3;
            #pragma unroll
            for (int off = 1; off < 16; off <<= 1)
                rs += __shfl_xor_sync(0xffffffffu, rs, off);
            l[i] = l[i]*fac + rs;
            m[i] = mn;
            #pragma unroll
            for (int c = 0; c < 6; c++) o[i][c] *= fac;
            float4 pw = make_float4(p0, p1, p2, p3);
            *(float4*)&Ps[(ty*4 + i)*68 + tx*4] = pw;
        }
        __syncthreads();

        // O += P @ V   (4 rows x 6 cols per thread)
        #pragma unroll 4
        for (int j4 = 0; j4 < 16; j4++) {
            float4 pv0 = *(float4*)&Ps[(ty*4 + 0)*68 + j4*4];
            float4 pv1 = *(float4*)&Ps[(ty*4 + 1)*68 + j4*4];
            float4 pv2 = *(float4*)&Ps[(ty*4 + 2)*68 + j4*4];
            float4 pv3 = *(float4*)&Ps[(ty*4 + 3)*68 + j4*4];
            float P0[4] = {pv0.x, pv0.y, pv0.z, pv0.w};
            float P1[4] = {pv1.x, pv1.y, pv1.z, pv1.w};
            float P2[4] = {pv2.x, pv2.y, pv2.z, pv2.w};
            float P3[4] = {pv3.x, pv3.y, pv3.z, pv3.w};
            #pragma unroll
            for (int jj = 0; jj < 4; jj++) {
                int j = j4*4 + jj;
                float2 v0 = *(float2*)&Vs[j*100 + tx*6];
                float2 v1 = *(float2*)&Vs[j*100 + tx*6 + 2];
                float2 v2 = *(float2*)&Vs[j*100 + tx*6 + 4];
                float vv[6] = {v0.x, v0.y, v1.x, v1.y, v2.x, v2.y};
                #pragma unroll
                for (int c = 0; c < 6; c++) {
                    o[0][c] += P0[jj]*vv[c];
                    o[1][c] += P1[jj]*vv[c];
                    o[2][c] += P2[jj]*vv[c];
                    o[3][c] += P3[jj]*vv[c];
                }
            }
        }
    }

    #pragma unroll
    for (int i = 0; i < 4; i++) {
        float inv = 1.f / l[i];
        long base = ((long)b*NN + qt*64 + ty*4 + i)*HH + h*DH + tx*6;
        #pragma unroll
        for (int c = 0; c < 6; c++) out[base + c] = o[i][c] * inv;
    }
}

// ---------------- host launcher ---------------------------------------------
static void sgemm(const float* A, const float* W, const float* bias,
                  const float* res, float* C, int M, int P, int K,
                  int act, int rowseg, long long segstride) {
    dim3 grid(K / 128, M / 128);
    sgemm_k<<<grid, 256>>>(A, W, bias, res, C, M, P, K, act, rowseg, segstride);
}

extern "C" void kernel_launch(void* const* d_in, const int* in_sizes, int n_in,
                              void* d_out, int out_size) {
    const int*   ids    = (const int*)  d_in[0];
    const float* vkey   = (const float*)d_in[1];   // [L,B,S,H]
    const float* vval   = (const float*)d_in[2];
    const float* embedW = (const float*)d_in[3];   // [V,H]
    const float* n1w    = (const float*)d_in[4];
    const float* n2w    = (const float*)d_in[5];
    const float* qkvW   = (const float*)d_in[6];   // [L,H,3H]
    const float* qkvB   = (const float*)d_in[7];
    const float* skvW   = (const float*)d_in[8];   // [L,H,H]
    const float* skvB   = (const float*)d_in[9];
    const float* outW   = (const float*)d_in[10];
    const float* outB   = (const float*)d_in[11];
    const float* f1W    = (const float*)d_in[12];
    const float* f1B    = (const float*)d_in[13];
    const float* f2W    = (const float*)d_in[14];
    const float* f2B    = (const float*)d_in[15];
    float* logits = (float*)d_out;

    float *hid, *x, *qkv, *q, *kc, *vc, *attn, *ffn, *eT, *ct, *st;
    cudaGetSymbolAddress((void**)&hid,  g_hidden);
    cudaGetSymbolAddress((void**)&x,    g_x);
    cudaGetSymbolAddress((void**)&qkv,  g_qkv);
    cudaGetSymbolAddress((void**)&q,    g_q);
    cudaGetSymbolAddress((void**)&kc,   g_kcat);
    cudaGetSymbolAddress((void**)&vc,   g_vcat);
    cudaGetSymbolAddress((void**)&attn, g_attn);
    cudaGetSymbolAddress((void**)&ffn,  g_ffn);
    cudaGetSymbolAddress((void**)&eT,   g_embedT);
    cudaGetSymbolAddress((void**)&ct,   g_cos);
    cudaGetSymbolAddress((void**)&st,   g_sin);

    static bool attr_set = false;
    if (!attr_set) {
        cudaFuncSetAttribute(attn2_k, cudaFuncAttributeMaxDynamicSharedMemorySize,
                             ATTN_SMEM);
        attr_set = true;
    }

    transpose_k<<<dim3(HH/32, VV/32), dim3(32, 8)>>>(embedW, eT);

    const int elemBlocks = (MROWS*HH + 255) / 256;
    embed_k<<<elemBlocks, 256>>>(ids, embedW, hid);
    rope_tab_k<<<(NN*DH + 255)/256, 256>>>(ct, st);

    const long HW  = (long)HH * HH;
    const long BSH = (long)BB * SS * HH;

    for (int l = 0; l < LN; l++) {
        rmsnorm_k<<<MROWS, 256>>>(hid, n1w + l*HH, x);
        sgemm(x, qkvW + (long)l*HH*3*HH, qkvB + l*3*HH, nullptr, qkv,
              MROWS, HH, 3*HH, 0, MROWS, 0);
        rope_split_k<<<elemBlocks, 256>>>(qkv, q, kc, vc, ct, st);
        sgemm(vkey + (long)l*BSH, skvW + l*HW, skvB + l*HH, nullptr, kc,
              MROWS, HH, HH, 0, SS, (long long)KVLEN*HH);
        sgemm(vval + (long)l*BSH, skvW + l*HW, skvB + l*HH, nullptr, vc,
              MROWS, HH, HH, 0, SS, (long long)KVLEN*HH);
        attn2_k<<<dim3(NN/64, NH, BB), 256, ATTN_SMEM>>>(q, kc, vc, attn);
        sgemm(attn, outW + l*HW, outB + l*HH, hid, hid,
              MROWS, HH, HH, 0, MROWS, 0);
        rmsnorm_k<<<MROWS, 256>>>(hid, n2w + l*HH, x);
        sgemm(x, f1W + l*HW, f1B + l*HH, nullptr, ffn,
              MROWS, HH, HH, 1, MROWS, 0);
        sgemm(ffn, f2W + l*HW, f2B + l*HH, hid, hid,
              MROWS, HH, HH, 0, MROWS, 0);
    }

    sgemm(hid, eT, nullptr, nullptr, logits, MROWS, HH, VV, 0, MROWS, 0);
}

// round 5
// speedup vs baseline: 3.8799x; 2.1228x over previous
#include <cuda_runtime.h>
#include <cuda_bf16.h>
#include <math.h>
#include <stdint.h>

// Problem constants
#define LN 12
#define BB 4
#define NN 512
#define SS 512
#define VV 32000
#define HH 768
#define NH 8
#define DH 96
#define MROWS (BB*NN)          // 2048
#define KVLEN (SS+NN)          // 1024

// ---------------- scratch (device globals; no allocation allowed) ----------
__device__ float g_hidden[MROWS*HH];
__device__ float g_x[MROWS*HH];
__device__ float g_qkv[MROWS*3*HH];
__device__ float g_q[MROWS*HH];
__device__ float g_kcat[BB*KVLEN*HH];
__device__ float g_vcat[BB*KVLEN*HH];
__device__ float g_attn[MROWS*HH];
__device__ float g_ffn[MROWS*HH];
__device__ float g_cos[NN*DH];
__device__ float g_sin[NN*DH];
// K-major transposed weights [l][N][K]
__device__ float g_qkvT[LN*3*HH*HH];
__device__ float g_skvT[LN*HH*HH];
__device__ float g_outT[LN*HH*HH];
__device__ float g_f1T[LN*HH*HH];
__device__ float g_f2T[LN*HH*HH];

// =================== helpers ================================================
__device__ __forceinline__ uint32_t smem_u32(const void* p) {
    uint32_t a;
    asm("{ .reg .u64 t; cvta.to.shared.u64 t, %1; cvt.u32.u64 %0, t; }"
        : "=r"(a) : "l"(p));
    return a;
}
__device__ __forceinline__ void sts128(uint32_t a, uint4 v) {
    asm volatile("st.shared.v4.b32 [%0], {%1,%2,%3,%4};"
        :: "r"(a), "r"(v.x), "r"(v.y), "r"(v.z), "r"(v.w) : "memory");
}
__device__ __forceinline__ void ldsm4(uint32_t (&r)[4], uint32_t addr) {
    asm volatile("ldmatrix.sync.aligned.m8n8.x4.shared.b16 {%0,%1,%2,%3}, [%4];"
        : "=r"(r[0]), "=r"(r[1]), "=r"(r[2]), "=r"(r[3]) : "r"(addr));
}
__device__ __forceinline__ void mma16816(float (&d)[4], const uint32_t (&a)[4],
                                         uint32_t b0, uint32_t b1) {
    asm volatile("mma.sync.aligned.m16n8k16.row.col.f32.bf16.bf16.f32 "
        "{%0,%1,%2,%3}, {%4,%5,%6,%7}, {%8,%9}, {%0,%1,%2,%3};"
        : "+f"(d[0]), "+f"(d[1]), "+f"(d[2]), "+f"(d[3])
        : "r"(a[0]), "r"(a[1]), "r"(a[2]), "r"(a[3]), "r"(b0), "r"(b1));
}
__device__ __forceinline__ uint32_t pk2(float x, float y) {
    __nv_bfloat162 t = __floats2bfloat162_rn(x, y);
    return *reinterpret_cast<uint32_t*>(&t);
}
__device__ __forceinline__ float hif(float x) {
    return __bfloat162float(__float2bfloat16_rn(x));
}
// 8 fp32 -> hi uint4 (4x bf16x2), lo uint4 (residual)
__device__ __forceinline__ void cvt8(float4 a, float4 b, uint4& hi, uint4& lo) {
    hi.x = pk2(a.x, a.y); hi.y = pk2(a.z, a.w);
    hi.z = pk2(b.x, b.y); hi.w = pk2(b.z, b.w);
    lo.x = pk2(a.x - hif(a.x), a.y - hif(a.y));
    lo.y = pk2(a.z - hif(a.z), a.w - hif(a.w));
    lo.z = pk2(b.x - hif(b.x), b.y - hif(b.y));
    lo.w = pk2(b.z - hif(b.z), b.w - hif(b.w));
}

// =================== mma.sync split-bf16 GEMM ===============================
// C[M,N] = A[M,P] @ BT[N,P]^T (+bias)(+res)(gelu). fp32 in/out, fp32 accum.
// CTA tile 64x128, K-slab 32, 8 warps (2x4), warp tile 32x32.
// Requires M%64==0, N%128==0, P%32==0.
#define KS 32
#define BMT 64
#define BNT 128
#define AHI 0
#define ALO 4096
#define BHI 8192
#define BLO 16384
#define STG 24576
#define GEMM_SMEM (2*STG)

__global__ __launch_bounds__(256, 2) void mgemm_k(
    const float* __restrict__ A, const float* __restrict__ BT,
    const float* __restrict__ bias, const float* res, float* __restrict__ C,
    int M, int P, int N, int act, int rowseg, long long segstride)
{
    extern __shared__ char smemb[];
    const uint32_t sb = smem_u32(smemb);
    const int tid = threadIdx.x, lane = tid & 31, wid = tid >> 5;
    const int wr = wid >> 2, wc = wid & 3;
    const int row0 = blockIdx.y * BMT, col0 = blockIdx.x * BNT;

    // ldmatrix per-lane addressing
    const int g = lane >> 3, ri = lane & 7;
    uint32_t aoff[2]; uint32_t asw[2];
    #pragma unroll
    for (int f = 0; f < 2; f++) {
        int m = wr*32 + f*16 + (g & 1)*8 + ri;
        aoff[f] = m * 64; asw[f] = (m >> 1) & 3;
    }
    const uint32_t qa = g >> 1;
    uint32_t boff[2]; uint32_t bsw[2];
    #pragma unroll
    for (int p = 0; p < 2; p++) {
        int n = wc*32 + p*16 + (g >> 1)*8 + ri;
        boff[p] = n * 64; bsw[p] = (n >> 1) & 3;
    }
    const uint32_t qb = g & 1;

    float acc[2][4][4];
    #pragma unroll
    for (int f = 0; f < 2; f++)
        #pragma unroll
        for (int j = 0; j < 4; j++)
            #pragma unroll
            for (int e = 0; e < 4; e++) acc[f][j][e] = 0.f;

    // staging: (BM+BN)*4 tasks / 256 threads = 3 per thread, 8 fp32 each
    int trow[3], tq[3];
    float4 s0[3], s1[3];
    #pragma unroll
    for (int it = 0; it < 3; it++) {
        int task = tid + it * 256;
        trow[it] = task >> 2; tq[it] = task & 3;
    }
    const int NS = P / KS;

    // preload slab 0
    {
        #pragma unroll
        for (int it = 0; it < 3; it++) {
            const float* src = (trow[it] < BMT)
                ? A + (long)(row0 + trow[it]) * P + tq[it]*8
                : BT + (long)(col0 + trow[it] - BMT) * P + tq[it]*8;
            s0[it] = *(const float4*)src;
            s1[it] = *(const float4*)(src + 4);
        }
        #pragma unroll
        for (int it = 0; it < 3; it++) {
            uint4 hi, lo; cvt8(s0[it], s1[it], hi, lo);
            int r = trow[it];
            if (r < BMT) {
                uint32_t off = r*64 + (((uint32_t)tq[it] ^ ((r>>1)&3)) << 4);
                sts128(sb + AHI + off, hi); sts128(sb + ALO + off, lo);
            } else {
                int rb = r - BMT;
                uint32_t off = rb*64 + (((uint32_t)tq[it] ^ ((rb>>1)&3)) << 4);
                sts128(sb + BHI + off, hi); sts128(sb + BLO + off, lo);
            }
        }
    }
    __syncthreads();

    for (int s = 0; s < NS; s++) {
        const uint32_t cb = sb + (s & 1) * STG;
        if (s + 1 < NS) {
            const int k0 = (s + 1) * KS;
            #pragma unroll
            for (int it = 0; it < 3; it++) {
                const float* src = (trow[it] < BMT)
                    ? A + (long)(row0 + trow[it]) * P + k0 + tq[it]*8
                    : BT + (long)(col0 + trow[it] - BMT) * P + k0 + tq[it]*8;
                s0[it] = *(const float4*)src;
                s1[it] = *(const float4*)(src + 4);
            }
        }

        #pragma unroll
        for (int kst = 0; kst < 2; kst++) {
            uint32_t ah[2][4], al[2][4], bh[2][4], bl[2][4];
            #pragma unroll
            for (int f = 0; f < 2; f++) {
                uint32_t off = aoff[f] + ((((uint32_t)(kst*2) + qa) ^ asw[f]) << 4);
                ldsm4(ah[f], cb + AHI + off);
                ldsm4(al[f], cb + ALO + off);
            }
            #pragma unroll
            for (int p = 0; p < 2; p++) {
                uint32_t off = boff[p] + ((((uint32_t)(kst*2) + qb) ^ bsw[p]) << 4);
                ldsm4(bh[p], cb + BHI + off);
                ldsm4(bl[p], cb + BLO + off);
            }
            #pragma unroll
            for (int f = 0; f < 2; f++)
                #pragma unroll
                for (int j = 0; j < 4; j++)
                    mma16816(acc[f][j], ah[f], bh[j>>1][(j&1)*2], bh[j>>1][(j&1)*2+1]);
            #pragma unroll
            for (int f = 0; f < 2; f++)
                #pragma unroll
                for (int j = 0; j < 4; j++)
                    mma16816(acc[f][j], ah[f], bl[j>>1][(j&1)*2], bl[j>>1][(j&1)*2+1]);
            #pragma unroll
            for (int f = 0; f < 2; f++)
                #pragma unroll
                for (int j = 0; j < 4; j++)
                    mma16816(acc[f][j], al[f], bh[j>>1][(j&1)*2], bh[j>>1][(j&1)*2+1]);
        }

        if (s + 1 < NS) {
            const uint32_t nb = sb + ((s + 1) & 1) * STG;
            #pragma unroll
            for (int it = 0; it < 3; it++) {
                uint4 hi, lo; cvt8(s0[it], s1[it], hi, lo);
                int r = trow[it];
                if (r < BMT) {
                    uint32_t off = r*64 + (((uint32_t)tq[it] ^ ((r>>1)&3)) << 4);
                    sts128(nb + AHI + off, hi); sts128(nb + ALO + off, lo);
                } else {
                    int rb = r - BMT;
                    uint32_t off = rb*64 + (((uint32_t)tq[it] ^ ((rb>>1)&3)) << 4);
                    sts128(nb + BHI + off, hi); sts128(nb + BLO + off, lo);
                }
            }
        }
        __syncthreads();
    }

    // epilogue
    #pragma unroll
    for (int f = 0; f < 2; f++) {
        #pragma unroll
        for (int j = 0; j < 4; j++) {
            int r = row0 + wr*32 + f*16 + (lane >> 2);
            int c = col0 + wc*32 + j*8 + (lane & 3)*2;
            #pragma unroll
            for (int half = 0; half < 2; half++) {
                int rr = r + half*8;
                float x0 = acc[f][j][half*2], x1 = acc[f][j][half*2+1];
                if (bias) { x0 += bias[c]; x1 += bias[c+1]; }
                if (res)  {
                    const float* rp = res + (long)rr*N + c;
                    x0 += rp[0]; x1 += rp[1];
                }
                if (act == 1) {
                    x0 = 0.5f*x0*(1.f + erff(x0*0.70710678118654752f));
                    x1 = 0.5f*x1*(1.f + erff(x1*0.70710678118654752f));
                }
                long ob = (long)(rr / rowseg) * segstride + (long)(rr % rowseg) * N + c;
                *(float2*)(C + ob) = make_float2(x0, x1);
            }
        }
    }
}

// ---------------- weight transpose: W[l][768][C] -> WT[l][C][768] -----------
__global__ void transpose_w_k(const float* __restrict__ W, float* __restrict__ WT, int C) {
    __shared__ float tile[32][33];
    int bx = blockIdx.x, by = blockIdx.y, z = blockIdx.z;
    int tx = threadIdx.x, ty = threadIdx.y;
    const float* src = W + (long)z * HH * C;
    float* dst = WT + (long)z * C * HH;
    #pragma unroll
    for (int j = 0; j < 32; j += 8)
        tile[ty + j][tx] = src[(long)(by * 32 + ty + j) * C + bx * 32 + tx];
    __syncthreads();
    #pragma unroll
    for (int j = 0; j < 32; j += 8)
        dst[(long)(bx * 32 + ty + j) * HH + by * 32 + tx] = tile[tx][ty + j];
}

// ---------------- embedding gather + scale ----------------------------------
__global__ void embed_k(const int* __restrict__ ids, const float* __restrict__ E,
                        float* __restrict__ hid) {
    long idx = (long)blockIdx.x * blockDim.x + threadIdx.x;
    if (idx >= (long)MROWS*HH) return;
    int col = (int)(idx % HH);
    long row = idx / HH;
    hid[idx] = E[(long)ids[row]*HH + col] * 27.712812921102035f; // sqrt(768)
}

// ---------------- RMSNorm (GemmaRMSNorm) ------------------------------------
__global__ __launch_bounds__(256) void rmsnorm_k(const float* __restrict__ x,
                                                 const float* __restrict__ w,
                                                 float* __restrict__ y) {
    int row = blockIdx.x;
    const float* xr = x + (long)row*HH;
    float s = 0.f;
    for (int c = threadIdx.x; c < HH; c += 256) { float v = xr[c]; s += v*v; }
    __shared__ float red[8];
    #pragma unroll
    for (int o = 16; o; o >>= 1) s += __shfl_xor_sync(~0u, s, o);
    if ((threadIdx.x & 31) == 0) red[threadIdx.x >> 5] = s;
    __syncthreads();
    if (threadIdx.x < 8) {
        float t = red[threadIdx.x];
        #pragma unroll
        for (int o = 4; o; o >>= 1) t += __shfl_xor_sync(0xffu, t, o);
        if (threadIdx.x == 0) red[0] = t;
    }
    __syncthreads();
    float inv = rsqrtf(red[0] / (float)HH + 1e-6f);
    for (int c = threadIdx.x; c < HH; c += 256)
        y[(long)row*HH + c] = xr[c] * inv * (1.f + w[c]);
}

// ---------------- RoPE cos/sin table ----------------------------------------
__global__ void rope_tab_k(float* __restrict__ ct, float* __restrict__ st) {
    int idx = blockIdx.x * blockDim.x + threadIdx.x;
    if (idx >= NN*DH) return;
    int n = idx / DH, dd = idx % DH;
    int t = (dd < DH/2) ? dd : dd - DH/2;
    float invf = __powf(10000.f, -((float)(2*t) / (float)DH));
    float fd = (float)n * invf;
    ct[idx] = cosf(fd);
    st[idx] = sinf(fd);
}

// ---------------- RoPE + q/k/v split-scatter --------------------------------
__global__ void rope_split_k(const float* __restrict__ qkv, float* __restrict__ qb,
                             float* __restrict__ kcat, float* __restrict__ vcat,
                             const float* __restrict__ ct, const float* __restrict__ st) {
    long idx = (long)blockIdx.x * blockDim.x + threadIdx.x;
    if (idx >= (long)MROWS*HH) return;
    int col = (int)(idx % HH);
    long row = idx / HH;
    int n = (int)(row % NN);
    int b = (int)(row / NN);
    int dd = col % DH;
    const float* base = qkv + row*(3*HH);
    float qv = base[col], kv = base[HH + col], vv = base[2*HH + col];
    float c = ct[n*DH + dd], s = st[n*DH + dd];
    float qrot = (dd < DH/2) ? -base[col + DH/2]      : base[col - DH/2];
    float krot = (dd < DH/2) ? -base[HH + col + DH/2] : base[HH + col - DH/2];
    qb[row*HH + col] = qv*c + qrot*s;
    long outk = ((long)b*KVLEN + SS + n)*HH + col;
    kcat[outk] = kv*c + krot*s;
    vcat[outk] = vv;
}

// ---------------- flash-style attention: 64q x 64kv tiles -------------------
#define QS_OFF 0
#define KS_OFF (96*68)
#define VS_OFF (2*96*68)
#define PS_OFF (2*96*68 + 64*100)
#define ATTN_SMEM ((2*96*68 + 64*100 + 64*68) * 4)

__global__ __launch_bounds__(256) void attn2_k(
    const float* __restrict__ q, const float* __restrict__ kcat,
    const float* __restrict__ vcat, float* __restrict__ out)
{
    extern __shared__ float sm[];
    float* Qs = sm + QS_OFF;
    float* Ks = sm + KS_OFF;
    float* Vs = sm + VS_OFF;
    float* Ps = sm + PS_OFF;

    const int qt = blockIdx.x, h = blockIdx.y, b = blockIdx.z;
    const int tid = threadIdx.x, tx = tid & 15, ty = tid >> 4;

    const float* qbase = q + ((long)b*NN + qt*64)*HH + h*DH;
    for (int c = tid; c < 64*24; c += 256) {
        int row = c / 24, k4 = (c % 24) * 4;
        float4 v = *(const float4*)(qbase + (long)row*HH + k4);
        Qs[(k4+0)*68 + row] = v.x;
        Qs[(k4+1)*68 + row] = v.y;
        Qs[(k4+2)*68 + row] = v.z;
        Qs[(k4+3)*68 + row] = v.w;
    }

    float m[4], l[4], o[4][6];
    #pragma unroll
    for (int i = 0; i < 4; i++) {
        m[i] = -3.0e38f; l[i] = 0.f;
        #pragma unroll
        for (int c = 0; c < 6; c++) o[i][c] = 0.f;
    }

    const float scale = 0.10206207261596575f; // 96^-0.5
    const int ntiles = SS/64 + qt + 1;
    const float* kb = kcat + (long)b*KVLEN*HH + h*DH;
    const float* vb = vcat + (long)b*KVLEN*HH + h*DH;

    for (int t = 0; t < ntiles; t++) {
        __syncthreads();
        for (int c = tid; c < 64*24; c += 256) {
            int row = c / 24, k4 = (c % 24) * 4;
            float4 kv = *(const float4*)(kb + (long)(t*64 + row)*HH + k4);
            Ks[(k4+0)*68 + row] = kv.x;
            Ks[(k4+1)*68 + row] = kv.y;
            Ks[(k4+2)*68 + row] = kv.z;
            Ks[(k4+3)*68 + row] = kv.w;
            float4 vv = *(const float4*)(vb + (long)(t*64 + row)*HH + k4);
            *(float4*)&Vs[row*100 + k4] = vv;
        }
        __syncthreads();

        float s[4][4];
        #pragma unroll
        for (int i = 0; i < 4; i++)
            #pragma unroll
            for (int j = 0; j < 4; j++) s[i][j] = 0.f;

        #pragma unroll 4
        for (int k = 0; k < DH; k++) {
            float4 qa = *(float4*)&Qs[k*68 + ty*4];
            float4 ka = *(float4*)&Ks[k*68 + tx*4];
            float av[4] = {qa.x, qa.y, qa.z, qa.w};
            float bv[4] = {ka.x, ka.y, ka.z, ka.w};
            #pragma unroll
            for (int i = 0; i < 4; i++)
                #pragma unroll
                for (int j = 0; j < 4; j++) s[i][j] += av[i] * bv[j];
        }

        const bool last = (t == ntiles - 1);
        #pragma unroll
        for (int i = 0; i < 4; i++) {
            #pragma unroll
            for (int j = 0; j < 4; j++) {
                float v = s[i][j] * scale;
                if (last && (tx*4 + j) > (ty*4 + i)) v = -1.0e30f;
                s[i][j] = v;
            }
        }

        #pragma unroll
        for (int i = 0; i < 4; i++) {
            float cm = fmaxf(fmaxf(s[i][0], s[i][1]), fmaxf(s[i][2], s[i][3]));
            #pragma unroll
            for (int off = 1; off < 16; off <<= 1)
                cm = fmaxf(cm, __shfl_xor_sync(0xffffffffu, cm, off));
            float mn = fmaxf(m[i], cm);
            float fac = __expf(m[i] - mn);
            float p0 = __expf(s[i][0] - mn);
            float p1 = __expf(s[i][1] - mn);
            float p2 = __expf(s[i][2] - mn);
            float p3 = __expf(s[i][3] - mn);
            float rs = p0 + p1 + p2 + p3;
            #pragma unroll
            for (int off = 1; off < 16; off <<= 1)
                rs += __shfl_xor_sync(0xffffffffu, rs, off);
            l[i] = l[i]*fac + rs;
            m[i] = mn;
            #pragma unroll
            for (int c = 0; c < 6; c++) o[i][c] *= fac;
            float4 pw = make_float4(p0, p1, p2, p3);
            *(float4*)&Ps[(ty*4 + i)*68 + tx*4] = pw;
        }
        __syncthreads();

        #pragma unroll 4
        for (int j4 = 0; j4 < 16; j4++) {
            float4 pv0 = *(float4*)&Ps[(ty*4 + 0)*68 + j4*4];
            float4 pv1 = *(float4*)&Ps[(ty*4 + 1)*68 + j4*4];
            float4 pv2 = *(float4*)&Ps[(ty*4 + 2)*68 + j4*4];
            float4 pv3 = *(float4*)&Ps[(ty*4 + 3)*68 + j4*4];
            float P0[4] = {pv0.x, pv0.y, pv0.z, pv0.w};
            float P1[4] = {pv1.x, pv1.y, pv1.z, pv1.w};
            float P2[4] = {pv2.x, pv2.y, pv2.z, pv2.w};
            float P3[4] = {pv3.x, pv3.y, pv3.z, pv3.w};
            #pragma unroll
            for (int jj = 0; jj < 4; jj++) {
                int j = j4*4 + jj;
                float2 v0 = *(float2*)&Vs[j*100 + tx*6];
                float2 v1 = *(float2*)&Vs[j*100 + tx*6 + 2];
                float2 v2 = *(float2*)&Vs[j*100 + tx*6 + 4];
                float vv[6] = {v0.x, v0.y, v1.x, v1.y, v2.x, v2.y};
                #pragma unroll
                for (int c = 0; c < 6; c++) {
                    o[0][c] += P0[jj]*vv[c];
                    o[1][c] += P1[jj]*vv[c];
                    o[2][c] += P2[jj]*vv[c];
                    o[3][c] += P3[jj]*vv[c];
                }
            }
        }
    }

    #pragma unroll
    for (int i = 0; i < 4; i++) {
        float inv = 1.f / l[i];
        long base = ((long)b*NN + qt*64 + ty*4 + i)*HH + h*DH + tx*6;
        #pragma unroll
        for (int c = 0; c < 6; c++) out[base + c] = o[i][c] * inv;
    }
}

// ---------------- host launcher ---------------------------------------------
static void mg(const float* A, const float* BT, const float* bias,
               const float* res, float* C, int M, int P, int N,
               int act, int rowseg, long long segstride) {
    dim3 grid(N / BNT, M / BMT);
    mgemm_k<<<grid, 256, GEMM_SMEM>>>(A, BT, bias, res, C, M, P, N,
                                      act, rowseg, segstride);
}

extern "C" void kernel_launch(void* const* d_in, const int* in_sizes, int n_in,
                              void* d_out, int out_size) {
    const int*   ids    = (const int*)  d_in[0];
    const float* vkey   = (const float*)d_in[1];   // [L,B,S,H]
    const float* vval   = (const float*)d_in[2];
    const float* embedW = (const float*)d_in[3];   // [V,H] (K-major for lm_head)
    const float* n1w    = (const float*)d_in[4];
    const float* n2w    = (const float*)d_in[5];
    const float* qkvW   = (const float*)d_in[6];   // [L,H,3H]
    const float* qkvB   = (const float*)d_in[7];
    const float* skvW   = (const float*)d_in[8];
    const float* skvB   = (const float*)d_in[9];
    const float* outW   = (const float*)d_in[10];
    const float* outB   = (const float*)d_in[11];
    const float* f1W    = (const float*)d_in[12];
    const float* f1B    = (const float*)d_in[13];
    const float* f2W    = (const float*)d_in[14];
    const float* f2B    = (const float*)d_in[15];
    float* logits = (float*)d_out;

    float *hid, *x, *qkv, *q, *kc, *vc, *attn, *ffn, *ct, *st;
    float *qkvT, *skvT, *outT, *f1T, *f2T;
    cudaGetSymbolAddress((void**)&hid,  g_hidden);
    cudaGetSymbolAddress((void**)&x,    g_x);
    cudaGetSymbolAddress((void**)&qkv,  g_qkv);
    cudaGetSymbolAddress((void**)&q,    g_q);
    cudaGetSymbolAddress((void**)&kc,   g_kcat);
    cudaGetSymbolAddress((void**)&vc,   g_vcat);
    cudaGetSymbolAddress((void**)&attn, g_attn);
    cudaGetSymbolAddress((void**)&ffn,  g_ffn);
    cudaGetSymbolAddress((void**)&ct,   g_cos);
    cudaGetSymbolAddress((void**)&st,   g_sin);
    cudaGetSymbolAddress((void**)&qkvT, g_qkvT);
    cudaGetSymbolAddress((void**)&skvT, g_skvT);
    cudaGetSymbolAddress((void**)&outT, g_outT);
    cudaGetSymbolAddress((void**)&f1T,  g_f1T);
    cudaGetSymbolAddress((void**)&f2T,  g_f2T);

    cudaFuncSetAttribute(attn2_k, cudaFuncAttributeMaxDynamicSharedMemorySize, ATTN_SMEM);
    cudaFuncSetAttribute(mgemm_k, cudaFuncAttributeMaxDynamicSharedMemorySize, GEMM_SMEM);

    // per-call weight transposes into K-major [N,K]
    transpose_w_k<<<dim3(3*HH/32, HH/32, LN), dim3(32, 8)>>>(qkvW, qkvT, 3*HH);
    transpose_w_k<<<dim3(HH/32, HH/32, LN), dim3(32, 8)>>>(skvW, skvT, HH);
    transpose_w_k<<<dim3(HH/32, HH/32, LN), dim3(32, 8)>>>(outW, outT, HH);
    transpose_w_k<<<dim3(HH/32, HH/32, LN), dim3(32, 8)>>>(f1W,  f1T,  HH);
    transpose_w_k<<<dim3(HH/32, HH/32, LN), dim3(32, 8)>>>(f2W,  f2T,  HH);

    const int elemBlocks = (MROWS*HH + 255) / 256;
    embed_k<<<elemBlocks, 256>>>(ids, embedW, hid);
    rope_tab_k<<<(NN*DH + 255)/256, 256>>>(ct, st);

    const long HW  = (long)HH * HH;
    const long BSH = (long)BB * SS * HH;

    for (int l = 0; l < LN; l++) {
        rmsnorm_k<<<MROWS, 256>>>(hid, n1w + l*HH, x);
        mg(x, qkvT + (long)l*3*HW, qkvB + l*3*HH, nullptr, qkv,
           MROWS, HH, 3*HH, 0, MROWS, 0);
        rope_split_k<<<elemBlocks, 256>>>(qkv, q, kc, vc, ct, st);
        mg(vkey + (long)l*BSH, skvT + l*HW, skvB + l*HH, nullptr, kc,
           MROWS, HH, HH, 0, SS, (long long)KVLEN*HH);
        mg(vval + (long)l*BSH, skvT + l*HW, skvB + l*HH, nullptr, vc,
           MROWS, HH, HH, 0, SS, (long long)KVLEN*HH);
        attn2_k<<<dim3(NN/64, NH, BB), 256, ATTN_SMEM>>>(q, kc, vc, attn);
        mg(attn, outT + l*HW, outB + l*HH, hid, hid,
           MROWS, HH, HH, 0, MROWS, 0);
        rmsnorm_k<<<MROWS, 256>>>(hid, n2w + l*HH, x);
        mg(x, f1T + l*HW, f1B + l*HH, nullptr, ffn,
           MROWS, HH, HH, 1, MROWS, 0);
        mg(ffn, f2T + l*HW, f2B + l*HH, hid, hid,
           MROWS, HH, HH, 0, MROWS, 0);
    }

    // tied lm_head: logits = hidden @ embed^T ; embedW is already [N=V, K=H]
    mg(hid, embedW, nullptr, nullptr, logits, MROWS, HH, VV, 0, MROWS, 0);
}

// round 6
// speedup vs baseline: 4.3026x; 1.1089x over previous
#include <cuda_runtime.h>
#include <cuda_bf16.h>
#include <cuda_fp16.h>
#include <math.h>
#include <stdint.h>

// Problem constants
#define LN 12
#define BB 4
#define NN 512
#define SS 512
#define VV 32000
#define HH 768
#define NH 8
#define DH 96
#define MROWS (BB*NN)          // 2048
#define KVLEN (SS+NN)          // 1024

// ---------------- scratch (device globals; no allocation allowed) ----------
__device__ float g_hidden[MROWS*HH];
__device__ float g_x[MROWS*HH];
__device__ float g_qkv[MROWS*3*HH];
__device__ float g_q[MROWS*HH];
__device__ float g_kcat[BB*KVLEN*HH];
__device__ float g_vcat[BB*KVLEN*HH];
__device__ float g_attn[MROWS*HH];
__device__ float g_ffn[MROWS*HH];
__device__ float g_cos[NN*DH];
__device__ float g_sin[NN*DH];
// K-major transposed weights [l][N][K]
__device__ float g_qkvT[LN*3*HH*HH];
__device__ float g_skvT[LN*HH*HH];
__device__ float g_outT[LN*HH*HH];
__device__ float g_f1T[LN*HH*HH];
__device__ float g_f2T[LN*HH*HH];

// =================== helpers ================================================
__device__ __forceinline__ uint32_t smem_u32(const void* p) {
    uint32_t a;
    asm("{ .reg .u64 t; cvta.to.shared.u64 t, %1; cvt.u32.u64 %0, t; }"
        : "=r"(a) : "l"(p));
    return a;
}
__device__ __forceinline__ void sts128(uint32_t a, uint4 v) {
    asm volatile("st.shared.v4.b32 [%0], {%1,%2,%3,%4};"
        :: "r"(a), "r"(v.x), "r"(v.y), "r"(v.z), "r"(v.w) : "memory");
}
__device__ __forceinline__ void ldsm4(uint32_t (&r)[4], uint32_t addr) {
    asm volatile("ldmatrix.sync.aligned.m8n8.x4.shared.b16 {%0,%1,%2,%3}, [%4];"
        : "=r"(r[0]), "=r"(r[1]), "=r"(r[2]), "=r"(r[3]) : "r"(addr));
}
__device__ __forceinline__ void mma16816(float (&d)[4], const uint32_t (&a)[4],
                                         uint32_t b0, uint32_t b1) {
    asm volatile("mma.sync.aligned.m16n8k16.row.col.f32.f16.f16.f32 "
        "{%0,%1,%2,%3}, {%4,%5,%6,%7}, {%8,%9}, {%0,%1,%2,%3};"
        : "+f"(d[0]), "+f"(d[1]), "+f"(d[2]), "+f"(d[3])
        : "r"(a[0]), "r"(a[1]), "r"(a[2]), "r"(a[3]), "r"(b0), "r"(b1));
}
__device__ __forceinline__ uint32_t pkh2(float x, float y) {
    __half2 t = __floats2half2_rn(x, y);
    return *reinterpret_cast<uint32_t*>(&t);
}
__device__ __forceinline__ float hifh(float x) {
    return __half2float(__float2half_rn(x));
}
// 8 fp32 -> hi uint4 (4x f16x2) and lo residual uint4
__device__ __forceinline__ void cvt8_hl(float4 a, float4 b, uint4& hi, uint4& lo) {
    hi.x = pkh2(a.x, a.y); hi.y = pkh2(a.z, a.w);
    hi.z = pkh2(b.x, b.y); hi.w = pkh2(b.z, b.w);
    lo.x = pkh2(a.x - hifh(a.x), a.y - hifh(a.y));
    lo.y = pkh2(a.z - hifh(a.z), a.w - hifh(a.w));
    lo.z = pkh2(b.x - hifh(b.x), b.y - hifh(b.y));
    lo.w = pkh2(b.z - hifh(b.z), b.w - hifh(b.w));
}
// 8 fp32 -> hi only
__device__ __forceinline__ void cvt8_h(float4 a, float4 b, uint4& hi) {
    hi.x = pkh2(a.x, a.y); hi.y = pkh2(a.z, a.w);
    hi.z = pkh2(b.x, b.y); hi.w = pkh2(b.z, b.w);
}

// =================== mma.sync split-fp16 GEMM (2-pass) ======================
// C[M,N] = A[M,P] @ BT[N,P]^T (+bias)(+res)(gelu). fp32 in/out, fp32 accum.
// A split hi/lo fp16 (compensated); B plain fp16.
// CTA tile 64x128, K-slab 32, 8 warps (2x4), warp tile 32x32.
// Requires M%64==0, N%128==0, P%32==0.
#define KS 32
#define BMT 64
#define BNT 128
#define AHI 0
#define ALO 4096
#define BHI 8192
#define STG 16384
#define GEMM_SMEM (2*STG)

__global__ __launch_bounds__(256, 2) void mgemm_k(
    const float* __restrict__ A, const float* __restrict__ BT,
    const float* __restrict__ bias, const float* res, float* __restrict__ C,
    int M, int P, int N, int act, int rowseg, long long segstride)
{
    extern __shared__ char smemb[];
    const uint32_t sb = smem_u32(smemb);
    const int tid = threadIdx.x, lane = tid & 31, wid = tid >> 5;
    const int wr = wid >> 2, wc = wid & 3;
    const int row0 = blockIdx.y * BMT, col0 = blockIdx.x * BNT;

    // ldmatrix per-lane addressing
    const int g = lane >> 3, ri = lane & 7;
    uint32_t aoff[2]; uint32_t asw[2];
    #pragma unroll
    for (int f = 0; f < 2; f++) {
        int m = wr*32 + f*16 + (g & 1)*8 + ri;
        aoff[f] = m * 64; asw[f] = (m >> 1) & 3;
    }
    const uint32_t qa = g >> 1;
    uint32_t boff[2]; uint32_t bsw[2];
    #pragma unroll
    for (int p = 0; p < 2; p++) {
        int n = wc*32 + p*16 + (g >> 1)*8 + ri;
        boff[p] = n * 64; bsw[p] = (n >> 1) & 3;
    }
    const uint32_t qb = g & 1;

    float acc[2][4][4];
    #pragma unroll
    for (int f = 0; f < 2; f++)
        #pragma unroll
        for (int j = 0; j < 4; j++)
            #pragma unroll
            for (int e = 0; e < 4; e++) acc[f][j][e] = 0.f;

    // staging: (BM+BN)*4 tasks / 256 threads = 3 per thread, 8 fp32 each
    int trow[3], tq[3];
    float4 s0[3], s1[3];
    #pragma unroll
    for (int it = 0; it < 3; it++) {
        int task = tid + it * 256;
        trow[it] = task >> 2; tq[it] = task & 3;
    }
    const int NS = P / KS;

    // preload slab 0
    {
        #pragma unroll
        for (int it = 0; it < 3; it++) {
            const float* src = (trow[it] < BMT)
                ? A + (long)(row0 + trow[it]) * P + tq[it]*8
                : BT + (long)(col0 + trow[it] - BMT) * P + tq[it]*8;
            s0[it] = *(const float4*)src;
            s1[it] = *(const float4*)(src + 4);
        }
        #pragma unroll
        for (int it = 0; it < 3; it++) {
            int r = trow[it];
            if (r < BMT) {
                uint4 hi, lo; cvt8_hl(s0[it], s1[it], hi, lo);
                uint32_t off = r*64 + (((uint32_t)tq[it] ^ ((r>>1)&3)) << 4);
                sts128(sb + AHI + off, hi); sts128(sb + ALO + off, lo);
            } else {
                uint4 hi; cvt8_h(s0[it], s1[it], hi);
                int rb = r - BMT;
                uint32_t off = rb*64 + (((uint32_t)tq[it] ^ ((rb>>1)&3)) << 4);
                sts128(sb + BHI + off, hi);
            }
        }
    }
    __syncthreads();

    for (int s = 0; s < NS; s++) {
        const uint32_t cb = sb + (s & 1) * STG;
        if (s + 1 < NS) {
            const int k0 = (s + 1) * KS;
            #pragma unroll
            for (int it = 0; it < 3; it++) {
                const float* src = (trow[it] < BMT)
                    ? A + (long)(row0 + trow[it]) * P + k0 + tq[it]*8
                    : BT + (long)(col0 + trow[it] - BMT) * P + k0 + tq[it]*8;
                s0[it] = *(const float4*)src;
                s1[it] = *(const float4*)(src + 4);
            }
        }

        #pragma unroll
        for (int kst = 0; kst < 2; kst++) {
            uint32_t ah[2][4], al[2][4], bh[2][4];
            #pragma unroll
            for (int f = 0; f < 2; f++) {
                uint32_t off = aoff[f] + ((((uint32_t)(kst*2) + qa) ^ asw[f]) << 4);
                ldsm4(ah[f], cb + AHI + off);
                ldsm4(al[f], cb + ALO + off);
            }
            #pragma unroll
            for (int p = 0; p < 2; p++) {
                uint32_t off = boff[p] + ((((uint32_t)(kst*2) + qb) ^ bsw[p]) << 4);
                ldsm4(bh[p], cb + BHI + off);
            }
            #pragma unroll
            for (int f = 0; f < 2; f++)
                #pragma unroll
                for (int j = 0; j < 4; j++)
                    mma16816(acc[f][j], ah[f], bh[j>>1][(j&1)*2], bh[j>>1][(j&1)*2+1]);
            #pragma unroll
            for (int f = 0; f < 2; f++)
                #pragma unroll
                for (int j = 0; j < 4; j++)
                    mma16816(acc[f][j], al[f], bh[j>>1][(j&1)*2], bh[j>>1][(j&1)*2+1]);
        }

        if (s + 1 < NS) {
            const uint32_t nb = sb + ((s + 1) & 1) * STG;
            #pragma unroll
            for (int it = 0; it < 3; it++) {
                int r = trow[it];
                if (r < BMT) {
                    uint4 hi, lo; cvt8_hl(s0[it], s1[it], hi, lo);
                    uint32_t off = r*64 + (((uint32_t)tq[it] ^ ((r>>1)&3)) << 4);
                    sts128(nb + AHI + off, hi); sts128(nb + ALO + off, lo);
                } else {
                    uint4 hi; cvt8_h(s0[it], s1[it], hi);
                    int rb = r - BMT;
                    uint32_t off = rb*64 + (((uint32_t)tq[it] ^ ((rb>>1)&3)) << 4);
                    sts128(nb + BHI + off, hi);
                }
            }
        }
        __syncthreads();
    }

    // epilogue
    #pragma unroll
    for (int f = 0; f < 2; f++) {
        #pragma unroll
        for (int j = 0; j < 4; j++) {
            int r = row0 + wr*32 + f*16 + (lane >> 2);
            int c = col0 + wc*32 + j*8 + (lane & 3)*2;
            #pragma unroll
            for (int half = 0; half < 2; half++) {
                int rr = r + half*8;
                float x0 = acc[f][j][half*2], x1 = acc[f][j][half*2+1];
                if (bias) { x0 += bias[c]; x1 += bias[c+1]; }
                if (res)  {
                    const float* rp = res + (long)rr*N + c;
                    x0 += rp[0]; x1 += rp[1];
                }
                if (act == 1) {
                    x0 = 0.5f*x0*(1.f + erff(x0*0.70710678118654752f));
                    x1 = 0.5f*x1*(1.f + erff(x1*0.70710678118654752f));
                }
                long ob = (long)(rr / rowseg) * segstride + (long)(rr % rowseg) * N + c;
                *(float2*)(C + ob) = make_float2(x0, x1);
            }
        }
    }
}

// ---------------- weight transpose: W[l][768][C] -> WT[l][C][768] -----------
__global__ void transpose_w_k(const float* __restrict__ W, float* __restrict__ WT, int C) {
    __shared__ float tile[32][33];
    int bx = blockIdx.x, by = blockIdx.y, z = blockIdx.z;
    int tx = threadIdx.x, ty = threadIdx.y;
    const float* src = W + (long)z * HH * C;
    float* dst = WT + (long)z * C * HH;
    #pragma unroll
    for (int j = 0; j < 32; j += 8)
        tile[ty + j][tx] = src[(long)(by * 32 + ty + j) * C + bx * 32 + tx];
    __syncthreads();
    #pragma unroll
    for (int j = 0; j < 32; j += 8)
        dst[(long)(bx * 32 + ty + j) * HH + by * 32 + tx] = tile[tx][ty + j];
}

// ---------------- embedding gather + scale ----------------------------------
__global__ void embed_k(const int* __restrict__ ids, const float* __restrict__ E,
                        float* __restrict__ hid) {
    long idx = (long)blockIdx.x * blockDim.x + threadIdx.x;
    if (idx >= (long)MROWS*HH) return;
    int col = (int)(idx % HH);
    long row = idx / HH;
    hid[idx] = E[(long)ids[row]*HH + col] * 27.712812921102035f; // sqrt(768)
}

// ---------------- RMSNorm (GemmaRMSNorm) ------------------------------------
__global__ __launch_bounds__(256) void rmsnorm_k(const float* __restrict__ x,
                                                 const float* __restrict__ w,
                                                 float* __restrict__ y) {
    int row = blockIdx.x;
    const float* xr = x + (long)row*HH;
    float s = 0.f;
    for (int c = threadIdx.x; c < HH; c += 256) { float v = xr[c]; s += v*v; }
    __shared__ float red[8];
    #pragma unroll
    for (int o = 16; o; o >>= 1) s += __shfl_xor_sync(~0u, s, o);
    if ((threadIdx.x & 31) == 0) red[threadIdx.x >> 5] = s;
    __syncthreads();
    if (threadIdx.x < 8) {
        float t = red[threadIdx.x];
        #pragma unroll
        for (int o = 4; o; o >>= 1) t += __shfl_xor_sync(0xffu, t, o);
        if (threadIdx.x == 0) red[0] = t;
    }
    __syncthreads();
    float inv = rsqrtf(red[0] / (float)HH + 1e-6f);
    for (int c = threadIdx.x; c < HH; c += 256)
        y[(long)row*HH + c] = xr[c] * inv * (1.f + w[c]);
}

// ---------------- RoPE cos/sin table ----------------------------------------
__global__ void rope_tab_k(float* __restrict__ ct, float* __restrict__ st) {
    int idx = blockIdx.x * blockDim.x + threadIdx.x;
    if (idx >= NN*DH) return;
    int n = idx / DH, dd = idx % DH;
    int t = (dd < DH/2) ? dd : dd - DH/2;
    float invf = __powf(10000.f, -((float)(2*t) / (float)DH));
    float fd = (float)n * invf;
    ct[idx] = cosf(fd);
    st[idx] = sinf(fd);
}

// ---------------- RoPE + q/k/v split-scatter --------------------------------
__global__ void rope_split_k(const float* __restrict__ qkv, float* __restrict__ qb,
                             float* __restrict__ kcat, float* __restrict__ vcat,
                             const float* __restrict__ ct, const float* __restrict__ st) {
    long idx = (long)blockIdx.x * blockDim.x + threadIdx.x;
    if (idx >= (long)MROWS*HH) return;
    int col = (int)(idx % HH);
    long row = idx / HH;
    int n = (int)(row % NN);
    int b = (int)(row / NN);
    int dd = col % DH;
    const float* base = qkv + row*(3*HH);
    float qv = base[col], kv = base[HH + col], vv = base[2*HH + col];
    float c = ct[n*DH + dd], s = st[n*DH + dd];
    float qrot = (dd < DH/2) ? -base[col + DH/2]      : base[col - DH/2];
    float krot = (dd < DH/2) ? -base[HH + col + DH/2] : base[HH + col - DH/2];
    qb[row*HH + col] = qv*c + qrot*s;
    long outk = ((long)b*KVLEN + SS + n)*HH + col;
    kcat[outk] = kv*c + krot*s;
    vcat[outk] = vv;
}

// ---------------- flash-style attention: 64q x 64kv tiles -------------------
#define QS_OFF 0
#define KS_OFF (96*68)
#define VS_OFF (2*96*68)
#define PS_OFF (2*96*68 + 64*100)
#define ATTN_SMEM ((2*96*68 + 64*100 + 64*68) * 4)

__global__ __launch_bounds__(256) void attn2_k(
    const float* __restrict__ q, const float* __restrict__ kcat,
    const float* __restrict__ vcat, float* __restrict__ out)
{
    extern __shared__ float sm[];
    float* Qs = sm + QS_OFF;
    float* Ks = sm + KS_OFF;
    float* Vs = sm + VS_OFF;
    float* Ps = sm + PS_OFF;

    const int qt = blockIdx.x, h = blockIdx.y, b = blockIdx.z;
    const int tid = threadIdx.x, tx = tid & 15, ty = tid >> 4;

    const float* qbase = q + ((long)b*NN + qt*64)*HH + h*DH;
    for (int c = tid; c < 64*24; c += 256) {
        int row = c / 24, k4 = (c % 24) * 4;
        float4 v = *(const float4*)(qbase + (long)row*HH + k4);
        Qs[(k4+0)*68 + row] = v.x;
        Qs[(k4+1)*68 + row] = v.y;
        Qs[(k4+2)*68 + row] = v.z;
        Qs[(k4+3)*68 + row] = v.w;
    }

    float m[4], l[4], o[4][6];
    #pragma unroll
    for (int i = 0; i < 4; i++) {
        m[i] = -3.0e38f; l[i] = 0.f;
        #pragma unroll
        for (int c = 0; c < 6; c++) o[i][c] = 0.f;
    }

    const float scale = 0.10206207261596575f; // 96^-0.5
    const int ntiles = SS/64 + qt + 1;
    const float* kb = kcat + (long)b*KVLEN*HH + h*DH;
    const float* vb = vcat + (long)b*KVLEN*HH + h*DH;

    for (int t = 0; t < ntiles; t++) {
        __syncthreads();
        for (int c = tid; c < 64*24; c += 256) {
            int row = c / 24, k4 = (c % 24) * 4;
            float4 kv = *(const float4*)(kb + (long)(t*64 + row)*HH + k4);
            Ks[(k4+0)*68 + row] = kv.x;
            Ks[(k4+1)*68 + row] = kv.y;
            Ks[(k4+2)*68 + row] = kv.z;
            Ks[(k4+3)*68 + row] = kv.w;
            float4 vv = *(const float4*)(vb + (long)(t*64 + row)*HH + k4);
            *(float4*)&Vs[row*100 + k4] = vv;
        }
        __syncthreads();

        float s[4][4];
        #pragma unroll
        for (int i = 0; i < 4; i++)
            #pragma unroll
            for (int j = 0; j < 4; j++) s[i][j] = 0.f;

        #pragma unroll 4
        for (int k = 0; k < DH; k++) {
            float4 qa = *(float4*)&Qs[k*68 + ty*4];
            float4 ka = *(float4*)&Ks[k*68 + tx*4];
            float av[4] = {qa.x, qa.y, qa.z, qa.w};
            float bv[4] = {ka.x, ka.y, ka.z, ka.w};
            #pragma unroll
            for (int i = 0; i < 4; i++)
                #pragma unroll
                for (int j = 0; j < 4; j++) s[i][j] += av[i] * bv[j];
        }

        const bool last = (t == ntiles - 1);
        #pragma unroll
        for (int i = 0; i < 4; i++) {
            #pragma unroll
            for (int j = 0; j < 4; j++) {
                float v = s[i][j] * scale;
                if (last && (tx*4 + j) > (ty*4 + i)) v = -1.0e30f;
                s[i][j] = v;
            }
        }

        #pragma unroll
        for (int i = 0; i < 4; i++) {
            float cm = fmaxf(fmaxf(s[i][0], s[i][1]), fmaxf(s[i][2], s[i][3]));
            #pragma unroll
            for (int off = 1; off < 16; off <<= 1)
                cm = fmaxf(cm, __shfl_xor_sync(0xffffffffu, cm, off));
            float mn = fmaxf(m[i], cm);
            float fac = __expf(m[i] - mn);
            float p0 = __expf(s[i][0] - mn);
            float p1 = __expf(s[i][1] - mn);
            float p2 = __expf(s[i][2] - mn);
            float p3 = __expf(s[i][3] - mn);
            float rs = p0 + p1 + p2 + p3;
            #pragma unroll
            for (int off = 1; off < 16; off <<= 1)
                rs += __shfl_xor_sync(0xffffffffu, rs, off);
            l[i] = l[i]*fac + rs;
            m[i] = mn;
            #pragma unroll
            for (int c = 0; c < 6; c++) o[i][c] *= fac;
            float4 pw = make_float4(p0, p1, p2, p3);
            *(float4*)&Ps[(ty*4 + i)*68 + tx*4] = pw;
        }
        __syncthreads();

        #pragma unroll 4
        for (int j4 = 0; j4 < 16; j4++) {
            float4 pv0 = *(float4*)&Ps[(ty*4 + 0)*68 + j4*4];
            float4 pv1 = *(float4*)&Ps[(ty*4 + 1)*68 + j4*4];
            float4 pv2 = *(float4*)&Ps[(ty*4 + 2)*68 + j4*4];
            float4 pv3 = *(float4*)&Ps[(ty*4 + 3)*68 + j4*4];
            float P0[4] = {pv0.x, pv0.y, pv0.z, pv0.w};
            float P1[4] = {pv1.x, pv1.y, pv1.z, pv1.w};
            float P2[4] = {pv2.x, pv2.y, pv2.z, pv2.w};
            float P3[4] = {pv3.x, pv3.y, pv3.z, pv3.w};
            #pragma unroll
            for (int jj = 0; jj < 4; jj++) {
                int j = j4*4 + jj;
                float2 v0 = *(float2*)&Vs[j*100 + tx*6];
                float2 v1 = *(float2*)&Vs[j*100 + tx*6 + 2];
                float2 v2 = *(float2*)&Vs[j*100 + tx*6 + 4];
                float vv[6] = {v0.x, v0.y, v1.x, v1.y, v2.x, v2.y};
                #pragma unroll
                for (int c = 0; c < 6; c++) {
                    o[0][c] += P0[jj]*vv[c];
                    o[1][c] += P1[jj]*vv[c];
                    o[2][c] += P2[jj]*vv[c];
                    o[3][c] += P3[jj]*vv[c];
                }
            }
        }
    }

    #pragma unroll
    for (int i = 0; i < 4; i++) {
        float inv = 1.f / l[i];
        long base = ((long)b*NN + qt*64 + ty*4 + i)*HH + h*DH + tx*6;
        #pragma unroll
        for (int c = 0; c < 6; c++) out[base + c] = o[i][c] * inv;
    }
}

// ---------------- host launcher ---------------------------------------------
static void mg(const float* A, const float* BT, const float* bias,
               const float* res, float* C, int M, int P, int N,
               int act, int rowseg, long long segstride) {
    dim3 grid(N / BNT, M / BMT);
    mgemm_k<<<grid, 256, GEMM_SMEM>>>(A, BT, bias, res, C, M, P, N,
                                      act, rowseg, segstride);
}

extern "C" void kernel_launch(void* const* d_in, const int* in_sizes, int n_in,
                              void* d_out, int out_size) {
    const int*   ids    = (const int*)  d_in[0];
    const float* vkey   = (const float*)d_in[1];   // [L,B,S,H]
    const float* vval   = (const float*)d_in[2];
    const float* embedW = (const float*)d_in[3];   // [V,H] (K-major for lm_head)
    const float* n1w    = (const float*)d_in[4];
    const float* n2w    = (const float*)d_in[5];
    const float* qkvW   = (const float*)d_in[6];   // [L,H,3H]
    const float* qkvB   = (const float*)d_in[7];
    const float* skvW   = (const float*)d_in[8];
    const float* skvB   = (const float*)d_in[9];
    const float* outW   = (const float*)d_in[10];
    const float* outB   = (const float*)d_in[11];
    const float* f1W    = (const float*)d_in[12];
    const float* f1B    = (const float*)d_in[13];
    const float* f2W    = (const float*)d_in[14];
    const float* f2B    = (const float*)d_in[15];
    float* logits = (float*)d_out;

    float *hid, *x, *qkv, *q, *kc, *vc, *attn, *ffn, *ct, *st;
    float *qkvT, *skvT, *outT, *f1T, *f2T;
    cudaGetSymbolAddress((void**)&hid,  g_hidden);
    cudaGetSymbolAddress((void**)&x,    g_x);
    cudaGetSymbolAddress((void**)&qkv,  g_qkv);
    cudaGetSymbolAddress((void**)&q,    g_q);
    cudaGetSymbolAddress((void**)&kc,   g_kcat);
    cudaGetSymbolAddress((void**)&vc,   g_vcat);
    cudaGetSymbolAddress((void**)&attn, g_attn);
    cudaGetSymbolAddress((void**)&ffn,  g_ffn);
    cudaGetSymbolAddress((void**)&ct,   g_cos);
    cudaGetSymbolAddress((void**)&st,   g_sin);
    cudaGetSymbolAddress((void**)&qkvT, g_qkvT);
    cudaGetSymbolAddress((void**)&skvT, g_skvT);
    cudaGetSymbolAddress((void**)&outT, g_outT);
    cudaGetSymbolAddress((void**)&f1T,  g_f1T);
    cudaGetSymbolAddress((void**)&f2T,  g_f2T);

    cudaFuncSetAttribute(attn2_k, cudaFuncAttributeMaxDynamicSharedMemorySize, ATTN_SMEM);
    cudaFuncSetAttribute(mgemm_k, cudaFuncAttributeMaxDynamicSharedMemorySize, GEMM_SMEM);

    // per-call weight transposes into K-major [N,K]
    transpose_w_k<<<dim3(3*HH/32, HH/32, LN), dim3(32, 8)>>>(qkvW, qkvT, 3*HH);
    transpose_w_k<<<dim3(HH/32, HH/32, LN), dim3(32, 8)>>>(skvW, skvT, HH);
    transpose_w_k<<<dim3(HH/32, HH/32, LN), dim3(32, 8)>>>(outW, outT, HH);
    transpose_w_k<<<dim3(HH/32, HH/32, LN), dim3(32, 8)>>>(f1W,  f1T,  HH);
    transpose_w_k<<<dim3(HH/32, HH/32, LN), dim3(32, 8)>>>(f2W,  f2T,  HH);

    const int elemBlocks = (MROWS*HH + 255) / 256;
    embed_k<<<elemBlocks, 256>>>(ids, embedW, hid);
    rope_tab_k<<<(NN*DH + 255)/256, 256>>>(ct, st);

    const long HW  = (long)HH * HH;
    const long BSH = (long)BB * SS * HH;

    for (int l = 0; l < LN; l++) {
        rmsnorm_k<<<MROWS, 256>>>(hid, n1w + l*HH, x);
        mg(x, qkvT + (long)l*3*HW, qkvB + l*3*HH, nullptr, qkv,
           MROWS, HH, 3*HH, 0, MROWS, 0);
        rope_split_k<<<elemBlocks, 256>>>(qkv, q, kc, vc, ct, st);
        mg(vkey + (long)l*BSH, skvT + l*HW, skvB + l*HH, nullptr, kc,
           MROWS, HH, HH, 0, SS, (long long)KVLEN*HH);
        mg(vval + (long)l*BSH, skvT + l*HW, skvB + l*HH, nullptr, vc,
           MROWS, HH, HH, 0, SS, (long long)KVLEN*HH);
        attn2_k<<<dim3(NN/64, NH, BB), 256, ATTN_SMEM>>>(q, kc, vc, attn);
        mg(attn, outT + l*HW, outB + l*HH, hid, hid,
           MROWS, HH, HH, 0, MROWS, 0);
        rmsnorm_k<<<MROWS, 256>>>(hid, n2w + l*HH, x);
        mg(x, f1T + l*HW, f1B + l*HH, nullptr, ffn,
           MROWS, HH, HH, 1, MROWS, 0);
        mg(ffn, f2T + l*HW, f2B + l*HH, hid, hid,
           MROWS, HH, HH, 0, MROWS, 0);
    }

    // tied lm_head: logits = hidden @ embed^T ; embedW is already [N=V, K=H]
    mg(hid, embedW, nullptr, nullptr, logits, MROWS, HH, VV, 0, MROWS, 0);
}

// round 7
// speedup vs baseline: 4.5716x; 1.0625x over previous
#include <cuda_runtime.h>
#include <cuda_bf16.h>
#include <cuda_fp16.h>
#include <math.h>
#include <stdint.h>

// Problem constants
#define LN 12
#define BB 4
#define NN 512
#define SS 512
#define VV 32000
#define HH 768
#define NH 8
#define DH 96
#define MROWS (BB*NN)          // 2048
#define KVLEN (SS+NN)          // 1024

// ---------------- scratch (device globals; no allocation allowed) ----------
__device__ float g_hidden[MROWS*HH];
__device__ float g_x[MROWS*HH];
__device__ float g_qkv[MROWS*3*HH];
__device__ float g_q[MROWS*HH];
__device__ float g_kcat[BB*KVLEN*HH];
__device__ float g_vcat[BB*KVLEN*HH];
__device__ float g_attn[MROWS*HH];
__device__ float g_ffn[MROWS*HH];
__device__ float g_cos[NN*DH];
__device__ float g_sin[NN*DH];
// K-major fp16 weights [l][N][K]
__device__ __half g_qkvTh[LN*3*HH*HH];
__device__ __half g_skvTh[LN*HH*HH];
__device__ __half g_outTh[LN*HH*HH];
__device__ __half g_f1Th[LN*HH*HH];
__device__ __half g_f2Th[LN*HH*HH];
__device__ __half g_embedh[(long)VV*HH];

// =================== helpers ================================================
__device__ __forceinline__ uint32_t smem_u32(const void* p) {
    uint32_t a;
    asm("{ .reg .u64 t; cvta.to.shared.u64 t, %1; cvt.u32.u64 %0, t; }"
        : "=r"(a) : "l"(p));
    return a;
}
__device__ __forceinline__ void sts128(uint32_t a, uint4 v) {
    asm volatile("st.shared.v4.b32 [%0], {%1,%2,%3,%4};"
        :: "r"(a), "r"(v.x), "r"(v.y), "r"(v.z), "r"(v.w) : "memory");
}
__device__ __forceinline__ void ldsm4(uint32_t (&r)[4], uint32_t addr) {
    asm volatile("ldmatrix.sync.aligned.m8n8.x4.shared.b16 {%0,%1,%2,%3}, [%4];"
        : "=r"(r[0]), "=r"(r[1]), "=r"(r[2]), "=r"(r[3]) : "r"(addr));
}
__device__ __forceinline__ void mma16816(float (&d)[4], const uint32_t (&a)[4],
                                         uint32_t b0, uint32_t b1) {
    asm volatile("mma.sync.aligned.m16n8k16.row.col.f32.f16.f16.f32 "
        "{%0,%1,%2,%3}, {%4,%5,%6,%7}, {%8,%9}, {%0,%1,%2,%3};"
        : "+f"(d[0]), "+f"(d[1]), "+f"(d[2]), "+f"(d[3])
        : "r"(a[0]), "r"(a[1]), "r"(a[2]), "r"(a[3]), "r"(b0), "r"(b1));
}
__device__ __forceinline__ uint32_t pkh2(float x, float y) {
    __half2 t = __floats2half2_rn(x, y);
    return *reinterpret_cast<uint32_t*>(&t);
}
__device__ __forceinline__ float hifh(float x) {
    return __half2float(__float2half_rn(x));
}
// 8 fp32 -> hi uint4 (4x f16x2) and lo residual uint4
__device__ __forceinline__ void cvt8_hl(float4 a, float4 b, uint4& hi, uint4& lo) {
    hi.x = pkh2(a.x, a.y); hi.y = pkh2(a.z, a.w);
    hi.z = pkh2(b.x, b.y); hi.w = pkh2(b.z, b.w);
    lo.x = pkh2(a.x - hifh(a.x), a.y - hifh(a.y));
    lo.y = pkh2(a.z - hifh(a.z), a.w - hifh(a.w));
    lo.z = pkh2(b.x - hifh(b.x), b.y - hifh(b.y));
    lo.w = pkh2(b.z - hifh(b.z), b.w - hifh(b.w));
}

// =================== mma.sync split-fp16 GEMM (2-pass) ======================
// C[M,N] = A[M,P] @ BT[N,P]^T (+bias)(+res)(gelu). A fp32 (hi/lo split in
// kernel), BT fp16 K-major (pre-converted). fp32 accumulate.
// CTA tile 128x128, K-slab 32, 16 warps (4x4), warp tile 32x32.
// Requires M%128==0, N%128==0, P%32==0.
#define KS 32
#define BMT 128
#define BNT 128
#define AHI 0
#define ALO 8192
#define BHI 16384
#define STG 24576
#define GEMM_SMEM (2*STG)

__global__ __launch_bounds__(512, 1) void mgemm_k(
    const float* __restrict__ A, const __half* __restrict__ BT,
    const float* __restrict__ bias, const float* res, float* __restrict__ C,
    int M, int P, int N, int act, int rowseg, long long segstride)
{
    extern __shared__ char smemb[];
    const uint32_t sb = smem_u32(smemb);
    const int tid = threadIdx.x, lane = tid & 31, wid = tid >> 5;
    const int wr = wid >> 2, wc = wid & 3;
    const int row0 = blockIdx.y * BMT, col0 = blockIdx.x * BNT;

    // ldmatrix per-lane addressing
    const int g = lane >> 3, ri = lane & 7;
    uint32_t aoff[2]; uint32_t asw[2];
    #pragma unroll
    for (int f = 0; f < 2; f++) {
        int m = wr*32 + f*16 + (g & 1)*8 + ri;
        aoff[f] = m * 64; asw[f] = (m >> 1) & 3;
    }
    const uint32_t qa = g >> 1;
    uint32_t boff[2]; uint32_t bsw[2];
    #pragma unroll
    for (int p = 0; p < 2; p++) {
        int n = wc*32 + p*16 + (g >> 1)*8 + ri;
        boff[p] = n * 64; bsw[p] = (n >> 1) & 3;
    }
    const uint32_t qb = g & 1;

    float acc[2][4][4];
    #pragma unroll
    for (int f = 0; f < 2; f++)
        #pragma unroll
        for (int j = 0; j < 4; j++)
            #pragma unroll
            for (int e = 0; e < 4; e++) acc[f][j][e] = 0.f;

    // staging: one (row, 16B-chunk) task per thread for A and for B
    const int ra = tid >> 2, qc = tid & 3;
    const uint32_t soff = ra*64 + (((uint32_t)qc ^ ((ra>>1)&3)) << 4);
    const float*  asrc = A  + (long)(row0 + ra) * P + qc*8;
    const __half* bsrc = BT + (long)(col0 + ra) * P + qc*8;
    const int NS = P / KS;

    float4 sA0, sA1; uint4 sB;
    // preload slab 0
    sA0 = *(const float4*)asrc;
    sA1 = *(const float4*)(asrc + 4);
    sB  = *(const uint4*)bsrc;
    {
        uint4 hi, lo; cvt8_hl(sA0, sA1, hi, lo);
        sts128(sb + AHI + soff, hi);
        sts128(sb + ALO + soff, lo);
        sts128(sb + BHI + soff, sB);
    }
    __syncthreads();

    for (int s = 0; s < NS; s++) {
        const uint32_t cb = sb + (s & 1) * STG;
        if (s + 1 < NS) {
            const int k0 = (s + 1) * KS;
            sA0 = *(const float4*)(asrc + k0);
            sA1 = *(const float4*)(asrc + k0 + 4);
            sB  = *(const uint4*)(bsrc + k0);
        }

        #pragma unroll
        for (int kst = 0; kst < 2; kst++) {
            uint32_t ah[2][4], al[2][4], bh[2][4];
            #pragma unroll
            for (int f = 0; f < 2; f++) {
                uint32_t off = aoff[f] + ((((uint32_t)(kst*2) + qa) ^ asw[f]) << 4);
                ldsm4(ah[f], cb + AHI + off);
                ldsm4(al[f], cb + ALO + off);
            }
            #pragma unroll
            for (int p = 0; p < 2; p++) {
                uint32_t off = boff[p] + ((((uint32_t)(kst*2) + qb) ^ bsw[p]) << 4);
                ldsm4(bh[p], cb + BHI + off);
            }
            #pragma unroll
            for (int f = 0; f < 2; f++)
                #pragma unroll
                for (int j = 0; j < 4; j++)
                    mma16816(acc[f][j], ah[f], bh[j>>1][(j&1)*2], bh[j>>1][(j&1)*2+1]);
            #pragma unroll
            for (int f = 0; f < 2; f++)
                #pragma unroll
                for (int j = 0; j < 4; j++)
                    mma16816(acc[f][j], al[f], bh[j>>1][(j&1)*2], bh[j>>1][(j&1)*2+1]);
        }

        if (s + 1 < NS) {
            const uint32_t nb = sb + ((s + 1) & 1) * STG;
            uint4 hi, lo; cvt8_hl(sA0, sA1, hi, lo);
            sts128(nb + AHI + soff, hi);
            sts128(nb + ALO + soff, lo);
            sts128(nb + BHI + soff, sB);
        }
        __syncthreads();
    }

    // epilogue
    #pragma unroll
    for (int f = 0; f < 2; f++) {
        #pragma unroll
        for (int j = 0; j < 4; j++) {
            int r = row0 + wr*32 + f*16 + (lane >> 2);
            int c = col0 + wc*32 + j*8 + (lane & 3)*2;
            #pragma unroll
            for (int half = 0; half < 2; half++) {
                int rr = r + half*8;
                float x0 = acc[f][j][half*2], x1 = acc[f][j][half*2+1];
                if (bias) { x0 += bias[c]; x1 += bias[c+1]; }
                if (res)  {
                    const float* rp = res + (long)rr*N + c;
                    x0 += rp[0]; x1 += rp[1];
                }
                if (act == 1) {
                    x0 = 0.5f*x0*(1.f + erff(x0*0.70710678118654752f));
                    x1 = 0.5f*x1*(1.f + erff(x1*0.70710678118654752f));
                }
                long ob = (long)(rr / rowseg) * segstride + (long)(rr % rowseg) * N + c;
                *(float2*)(C + ob) = make_float2(x0, x1);
            }
        }
    }
}

// ---------------- weight transpose+fp16: W[l][768][C] -> WT[l][C][768] ------
__global__ void transpose_wh_k(const float* __restrict__ W, __half* __restrict__ WT,
                               int C) {
    __shared__ float tile[32][33];
    int bx = blockIdx.x, by = blockIdx.y, z = blockIdx.z;
    int tx = threadIdx.x, ty = threadIdx.y;
    const float* src = W + (long)z * HH * C;
    __half* dst = WT + (long)z * C * HH;
    #pragma unroll
    for (int j = 0; j < 32; j += 8)
        tile[ty + j][tx] = src[(long)(by * 32 + ty + j) * C + bx * 32 + tx];
    __syncthreads();
    #pragma unroll
    for (int j = 0; j < 32; j += 8)
        dst[(long)(bx * 32 + ty + j) * HH + by * 32 + tx] =
            __float2half_rn(tile[tx][ty + j]);
}

// ---------------- fp32 -> fp16 elementwise ----------------------------------
__global__ void cvt_half_k(const float* __restrict__ E, __half* __restrict__ O,
                           long n) {
    long i = (long)blockIdx.x * blockDim.x + threadIdx.x;
    if (i < n) O[i] = __float2half_rn(E[i]);
}

// ---------------- embedding gather + scale ----------------------------------
__global__ void embed_k(const int* __restrict__ ids, const float* __restrict__ E,
                        float* __restrict__ hid) {
    long idx = (long)blockIdx.x * blockDim.x + threadIdx.x;
    if (idx >= (long)MROWS*HH) return;
    int col = (int)(idx % HH);
    long row = idx / HH;
    hid[idx] = E[(long)ids[row]*HH + col] * 27.712812921102035f; // sqrt(768)
}

// ---------------- RMSNorm (GemmaRMSNorm) ------------------------------------
__global__ __launch_bounds__(256) void rmsnorm_k(const float* __restrict__ x,
                                                 const float* __restrict__ w,
                                                 float* __restrict__ y) {
    int row = blockIdx.x;
    const float* xr = x + (long)row*HH;
    float s = 0.f;
    for (int c = threadIdx.x; c < HH; c += 256) { float v = xr[c]; s += v*v; }
    __shared__ float red[8];
    #pragma unroll
    for (int o = 16; o; o >>= 1) s += __shfl_xor_sync(~0u, s, o);
    if ((threadIdx.x & 31) == 0) red[threadIdx.x >> 5] = s;
    __syncthreads();
    if (threadIdx.x < 8) {
        float t = red[threadIdx.x];
        #pragma unroll
        for (int o = 4; o; o >>= 1) t += __shfl_xor_sync(0xffu, t, o);
        if (threadIdx.x == 0) red[0] = t;
    }
    __syncthreads();
    float inv = rsqrtf(red[0] / (float)HH + 1e-6f);
    for (int c = threadIdx.x; c < HH; c += 256)
        y[(long)row*HH + c] = xr[c] * inv * (1.f + w[c]);
}

// ---------------- RoPE cos/sin table ----------------------------------------
__global__ void rope_tab_k(float* __restrict__ ct, float* __restrict__ st) {
    int idx = blockIdx.x * blockDim.x + threadIdx.x;
    if (idx >= NN*DH) return;
    int n = idx / DH, dd = idx % DH;
    int t = (dd < DH/2) ? dd : dd - DH/2;
    float invf = __powf(10000.f, -((float)(2*t) / (float)DH));
    float fd = (float)n * invf;
    ct[idx] = cosf(fd);
    st[idx] = sinf(fd);
}

// ---------------- RoPE + q/k/v split-scatter --------------------------------
__global__ void rope_split_k(const float* __restrict__ qkv, float* __restrict__ qb,
                             float* __restrict__ kcat, float* __restrict__ vcat,
                             const float* __restrict__ ct, const float* __restrict__ st) {
    long idx = (long)blockIdx.x * blockDim.x + threadIdx.x;
    if (idx >= (long)MROWS*HH) return;
    int col = (int)(idx % HH);
    long row = idx / HH;
    int n = (int)(row % NN);
    int b = (int)(row / NN);
    int dd = col % DH;
    const float* base = qkv + row*(3*HH);
    float qv = base[col], kv = base[HH + col], vv = base[2*HH + col];
    float c = ct[n*DH + dd], s = st[n*DH + dd];
    float qrot = (dd < DH/2) ? -base[col + DH/2]      : base[col - DH/2];
    float krot = (dd < DH/2) ? -base[HH + col + DH/2] : base[HH + col - DH/2];
    qb[row*HH + col] = qv*c + qrot*s;
    long outk = ((long)b*KVLEN + SS + n)*HH + col;
    kcat[outk] = kv*c + krot*s;
    vcat[outk] = vv;
}

// ---------------- flash-style attention: 64q x 64kv tiles -------------------
#define QS_OFF 0
#define KS_OFF (96*68)
#define VS_OFF (2*96*68)
#define PS_OFF (2*96*68 + 64*100)
#define ATTN_SMEM ((2*96*68 + 64*100 + 64*68) * 4)

__global__ __launch_bounds__(256) void attn2_k(
    const float* __restrict__ q, const float* __restrict__ kcat,
    const float* __restrict__ vcat, float* __restrict__ out)
{
    extern __shared__ float sm[];
    float* Qs = sm + QS_OFF;
    float* Ks = sm + KS_OFF;
    float* Vs = sm + VS_OFF;
    float* Ps = sm + PS_OFF;

    const int qt = blockIdx.x, h = blockIdx.y, b = blockIdx.z;
    const int tid = threadIdx.x, tx = tid & 15, ty = tid >> 4;

    const float* qbase = q + ((long)b*NN + qt*64)*HH + h*DH;
    for (int c = tid; c < 64*24; c += 256) {
        int row = c / 24, k4 = (c % 24) * 4;
        float4 v = *(const float4*)(qbase + (long)row*HH + k4);
        Qs[(k4+0)*68 + row] = v.x;
        Qs[(k4+1)*68 + row] = v.y;
        Qs[(k4+2)*68 + row] = v.z;
        Qs[(k4+3)*68 + row] = v.w;
    }

    float m[4], l[4], o[4][6];
    #pragma unroll
    for (int i = 0; i < 4; i++) {
        m[i] = -3.0e38f; l[i] = 0.f;
        #pragma unroll
        for (int c = 0; c < 6; c++) o[i][c] = 0.f;
    }

    const float scale = 0.10206207261596575f; // 96^-0.5
    const int ntiles = SS/64 + qt + 1;
    const float* kb = kcat + (long)b*KVLEN*HH + h*DH;
    const float* vb = vcat + (long)b*KVLEN*HH + h*DH;

    for (int t = 0; t < ntiles; t++) {
        __syncthreads();
        for (int c = tid; c < 64*24; c += 256) {
            int row = c / 24, k4 = (c % 24) * 4;
            float4 kv = *(const float4*)(kb + (long)(t*64 + row)*HH + k4);
            Ks[(k4+0)*68 + row] = kv.x;
            Ks[(k4+1)*68 + row] = kv.y;
            Ks[(k4+2)*68 + row] = kv.z;
            Ks[(k4+3)*68 + row] = kv.w;
            float4 vv = *(const float4*)(vb + (long)(t*64 + row)*HH + k4);
            *(float4*)&Vs[row*100 + k4] = vv;
        }
        __syncthreads();

        float s[4][4];
        #pragma unroll
        for (int i = 0; i < 4; i++)
            #pragma unroll
            for (int j = 0; j < 4; j++) s[i][j] = 0.f;

        #pragma unroll 4
        for (int k = 0; k < DH; k++) {
            float4 qa = *(float4*)&Qs[k*68 + ty*4];
            float4 ka = *(float4*)&Ks[k*68 + tx*4];
            float av[4] = {qa.x, qa.y, qa.z, qa.w};
            float bv[4] = {ka.x, ka.y, ka.z, ka.w};
            #pragma unroll
            for (int i = 0; i < 4; i++)
                #pragma unroll
                for (int j = 0; j < 4; j++) s[i][j] += av[i] * bv[j];
        }

        const bool last = (t == ntiles - 1);
        #pragma unroll
        for (int i = 0; i < 4; i++) {
            #pragma unroll
            for (int j = 0; j < 4; j++) {
                float v = s[i][j] * scale;
                if (last && (tx*4 + j) > (ty*4 + i)) v = -1.0e30f;
                s[i][j] = v;
            }
        }

        #pragma unroll
        for (int i = 0; i < 4; i++) {
            float cm = fmaxf(fmaxf(s[i][0], s[i][1]), fmaxf(s[i][2], s[i][3]));
            #pragma unroll
            for (int off = 1; off < 16; off <<= 1)
                cm = fmaxf(cm, __shfl_xor_sync(0xffffffffu, cm, off));
            float mn = fmaxf(m[i], cm);
            float fac = __expf(m[i] - mn);
            float p0 = __expf(s[i][0] - mn);
            float p1 = __expf(s[i][1] - mn);
            float p2 = __expf(s[i][2] - mn);
            float p3 = __expf(s[i][3] - mn);
            float rs = p0 + p1 + p2 + p3;
            #pragma unroll
            for (int off = 1; off < 16; off <<= 1)
                rs += __shfl_xor_sync(0xffffffffu, rs, off);
            l[i] = l[i]*fac + rs;
            m[i] = mn;
            #pragma unroll
            for (int c = 0; c < 6; c++) o[i][c] *= fac;
            float4 pw = make_float4(p0, p1, p2, p3);
            *(float4*)&Ps[(ty*4 + i)*68 + tx*4] = pw;
        }
        __syncthreads();

        #pragma unroll 4
        for (int j4 = 0; j4 < 16; j4++) {
            float4 pv0 = *(float4*)&Ps[(ty*4 + 0)*68 + j4*4];
            float4 pv1 = *(float4*)&Ps[(ty*4 + 1)*68 + j4*4];
            float4 pv2 = *(float4*)&Ps[(ty*4 + 2)*68 + j4*4];
            float4 pv3 = *(float4*)&Ps[(ty*4 + 3)*68 + j4*4];
            float P0[4] = {pv0.x, pv0.y, pv0.z, pv0.w};
            float P1[4] = {pv1.x, pv1.y, pv1.z, pv1.w};
            float P2[4] = {pv2.x, pv2.y, pv2.z, pv2.w};
            float P3[4] = {pv3.x, pv3.y, pv3.z, pv3.w};
            #pragma unroll
            for (int jj = 0; jj < 4; jj++) {
                int j = j4*4 + jj;
                float2 v0 = *(float2*)&Vs[j*100 + tx*6];
                float2 v1 = *(float2*)&Vs[j*100 + tx*6 + 2];
                float2 v2 = *(float2*)&Vs[j*100 + tx*6 + 4];
                float vv[6] = {v0.x, v0.y, v1.x, v1.y, v2.x, v2.y};
                #pragma unroll
                for (int c = 0; c < 6; c++) {
                    o[0][c] += P0[jj]*vv[c];
                    o[1][c] += P1[jj]*vv[c];
                    o[2][c] += P2[jj]*vv[c];
                    o[3][c] += P3[jj]*vv[c];
                }
            }
        }
    }

    #pragma unroll
    for (int i = 0; i < 4; i++) {
        float inv = 1.f / l[i];
        long base = ((long)b*NN + qt*64 + ty*4 + i)*HH + h*DH + tx*6;
        #pragma unroll
        for (int c = 0; c < 6; c++) out[base + c] = o[i][c] * inv;
    }
}

// ---------------- host launcher ---------------------------------------------
static void mg(const float* A, const __half* BT, const float* bias,
               const float* res, float* C, int M, int P, int N,
               int act, int rowseg, long long segstride) {
    dim3 grid(N / BNT, M / BMT);
    mgemm_k<<<grid, 512, GEMM_SMEM>>>(A, BT, bias, res, C, M, P, N,
                                      act, rowseg, segstride);
}

extern "C" void kernel_launch(void* const* d_in, const int* in_sizes, int n_in,
                              void* d_out, int out_size) {
    const int*   ids    = (const int*)  d_in[0];
    const float* vkey   = (const float*)d_in[1];   // [L,B,S,H]
    const float* vval   = (const float*)d_in[2];
    const float* embedW = (const float*)d_in[3];   // [V,H]
    const float* n1w    = (const float*)d_in[4];
    const float* n2w    = (const float*)d_in[5];
    const float* qkvW   = (const float*)d_in[6];   // [L,H,3H]
    const float* qkvB   = (const float*)d_in[7];
    const float* skvW   = (const float*)d_in[8];
    const float* skvB   = (const float*)d_in[9];
    const float* outW   = (const float*)d_in[10];
    const float* outB   = (const float*)d_in[11];
    const float* f1W    = (const float*)d_in[12];
    const float* f1B    = (const float*)d_in[13];
    const float* f2W    = (const float*)d_in[14];
    const float* f2B    = (const float*)d_in[15];
    float* logits = (float*)d_out;

    float *hid, *x, *qkv, *q, *kc, *vc, *attn, *ffn, *ct, *st;
    __half *qkvTh, *skvTh, *outTh, *f1Th, *f2Th, *embh;
    cudaGetSymbolAddress((void**)&hid,   g_hidden);
    cudaGetSymbolAddress((void**)&x,     g_x);
    cudaGetSymbolAddress((void**)&qkv,   g_qkv);
    cudaGetSymbolAddress((void**)&q,     g_q);
    cudaGetSymbolAddress((void**)&kc,    g_kcat);
    cudaGetSymbolAddress((void**)&vc,    g_vcat);
    cudaGetSymbolAddress((void**)&attn,  g_attn);
    cudaGetSymbolAddress((void**)&ffn,   g_ffn);
    cudaGetSymbolAddress((void**)&ct,    g_cos);
    cudaGetSymbolAddress((void**)&st,    g_sin);
    cudaGetSymbolAddress((void**)&qkvTh, g_qkvTh);
    cudaGetSymbolAddress((void**)&skvTh, g_skvTh);
    cudaGetSymbolAddress((void**)&outTh, g_outTh);
    cudaGetSymbolAddress((void**)&f1Th,  g_f1Th);
    cudaGetSymbolAddress((void**)&f2Th,  g_f2Th);
    cudaGetSymbolAddress((void**)&embh,  g_embedh);

    cudaFuncSetAttribute(attn2_k, cudaFuncAttributeMaxDynamicSharedMemorySize, ATTN_SMEM);
    cudaFuncSetAttribute(mgemm_k, cudaFuncAttributeMaxDynamicSharedMemorySize, GEMM_SMEM);

    // per-call weight transposes into K-major fp16 [N,K]
    transpose_wh_k<<<dim3(3*HH/32, HH/32, LN), dim3(32, 8)>>>(qkvW, qkvTh, 3*HH);
    transpose_wh_k<<<dim3(HH/32, HH/32, LN), dim3(32, 8)>>>(skvW, skvTh, HH);
    transpose_wh_k<<<dim3(HH/32, HH/32, LN), dim3(32, 8)>>>(outW, outTh, HH);
    transpose_wh_k<<<dim3(HH/32, HH/32, LN), dim3(32, 8)>>>(f1W,  f1Th,  HH);
    transpose_wh_k<<<dim3(HH/32, HH/32, LN), dim3(32, 8)>>>(f2W,  f2Th,  HH);
    // embed fp16 copy for lm_head (already K-major [V,H])
    {
        long n = (long)VV * HH;
        cvt_half_k<<<(int)((n + 255) / 256), 256>>>(embedW, embh, n);
    }

    const int elemBlocks = (MROWS*HH + 255) / 256;
    embed_k<<<elemBlocks, 256>>>(ids, embedW, hid);
    rope_tab_k<<<(NN*DH + 255)/256, 256>>>(ct, st);

    const long HW  = (long)HH * HH;
    const long BSH = (long)BB * SS * HH;

    for (int l = 0; l < LN; l++) {
        rmsnorm_k<<<MROWS, 256>>>(hid, n1w + l*HH, x);
        mg(x, qkvTh + (long)l*3*HW, qkvB + l*3*HH, nullptr, qkv,
           MROWS, HH, 3*HH, 0, MROWS, 0);
        rope_split_k<<<elemBlocks, 256>>>(qkv, q, kc, vc, ct, st);
        mg(vkey + (long)l*BSH, skvTh + l*HW, skvB + l*HH, nullptr, kc,
           MROWS, HH, HH, 0, SS, (long long)KVLEN*HH);
        mg(vval + (long)l*BSH, skvTh + l*HW, skvB + l*HH, nullptr, vc,
           MROWS, HH, HH, 0, SS, (long long)KVLEN*HH);
        attn2_k<<<dim3(NN/64, NH, BB), 256, ATTN_SMEM>>>(q, kc, vc, attn);
        mg(attn, outTh + l*HW, outB + l*HH, hid, hid,
           MROWS, HH, HH, 0, MROWS, 0);
        rmsnorm_k<<<MROWS, 256>>>(hid, n2w + l*HH, x);
        mg(x, f1Th + l*HW, f1B + l*HH, nullptr, ffn,
           MROWS, HH, HH, 1, MROWS, 0);
        mg(ffn, f2Th + l*HW, f2B + l*HH, hid, hid,
           MROWS, HH, HH, 0, MROWS, 0);
    }

    // tied lm_head: logits = hidden @ embed^T ; embedh is [N=V, K=H] fp16
    mg(hid, embh, nullptr, nullptr, logits, MROWS, HH, VV, 0, MROWS, 0);
}

// round 8
// speedup vs baseline: 6.9454x; 1.5192x over previous
#include <cuda_runtime.h>
#include <cuda_bf16.h>
#include <cuda_fp16.h>
#include <math.h>
#include <stdint.h>

// Problem constants
#define LN 12
#define BB 4
#define NN 512
#define SS 512
#define VV 32000
#define HH 768
#define NH 8
#define DH 96
#define MROWS (BB*NN)          // 2048
#define KVLEN (SS+NN)          // 1024

// ---------------- scratch (device globals; no allocation allowed) ----------
__device__ float g_hidden[MROWS*HH];
__device__ float g_x[MROWS*HH];
__device__ float g_qkv[MROWS*3*HH];
__device__ float g_q[MROWS*HH];
__device__ float g_kcat[BB*KVLEN*HH];
__device__ float g_vcat[BB*KVLEN*HH];
__device__ float g_attn[MROWS*HH];
__device__ float g_ffn[MROWS*HH];
__device__ float g_cos[NN*DH];
__device__ float g_sin[NN*DH];
// K-major fp16 weights [l][N][K]
__device__ __half g_qkvTh[LN*3*HH*HH];
__device__ __half g_skvTh[LN*HH*HH];
__device__ __half g_outTh[LN*HH*HH];
__device__ __half g_f1Th[LN*HH*HH];
__device__ __half g_f2Th[LN*HH*HH];
__device__ __half g_embedh[(long)VV*HH];

// =================== helpers ================================================
__device__ __forceinline__ uint32_t smem_u32(const void* p) {
    uint32_t a;
    asm("{ .reg .u64 t; cvta.to.shared.u64 t, %1; cvt.u32.u64 %0, t; }"
        : "=r"(a) : "l"(p));
    return a;
}
__device__ __forceinline__ void sts128(uint32_t a, uint4 v) {
    asm volatile("st.shared.v4.b32 [%0], {%1,%2,%3,%4};"
        :: "r"(a), "r"(v.x), "r"(v.y), "r"(v.z), "r"(v.w) : "memory");
}
__device__ __forceinline__ void ldsm4(uint32_t (&r)[4], uint32_t addr) {
    asm volatile("ldmatrix.sync.aligned.m8n8.x4.shared.b16 {%0,%1,%2,%3}, [%4];"
        : "=r"(r[0]), "=r"(r[1]), "=r"(r[2]), "=r"(r[3]) : "r"(addr));
}
__device__ __forceinline__ void ldsm4t(uint32_t (&r)[4], uint32_t addr) {
    asm volatile("ldmatrix.sync.aligned.m8n8.x4.trans.shared.b16 {%0,%1,%2,%3}, [%4];"
        : "=r"(r[0]), "=r"(r[1]), "=r"(r[2]), "=r"(r[3]) : "r"(addr));
}
__device__ __forceinline__ void mma16816(float (&d)[4], const uint32_t (&a)[4],
                                         uint32_t b0, uint32_t b1) {
    asm volatile("mma.sync.aligned.m16n8k16.row.col.f32.f16.f16.f32 "
        "{%0,%1,%2,%3}, {%4,%5,%6,%7}, {%8,%9}, {%0,%1,%2,%3};"
        : "+f"(d[0]), "+f"(d[1]), "+f"(d[2]), "+f"(d[3])
        : "r"(a[0]), "r"(a[1]), "r"(a[2]), "r"(a[3]), "r"(b0), "r"(b1));
}
__device__ __forceinline__ uint32_t pkh2(float x, float y) {
    __half2 t = __floats2half2_rn(x, y);
    return *reinterpret_cast<uint32_t*>(&t);
}
__device__ __forceinline__ float hifh(float x) {
    return __half2float(__float2half_rn(x));
}
// 8 fp32 -> hi uint4 (4x f16x2) and lo residual uint4
__device__ __forceinline__ void cvt8_hl(float4 a, float4 b, uint4& hi, uint4& lo) {
    hi.x = pkh2(a.x, a.y); hi.y = pkh2(a.z, a.w);
    hi.z = pkh2(b.x, b.y); hi.w = pkh2(b.z, b.w);
    lo.x = pkh2(a.x - hifh(a.x), a.y - hifh(a.y));
    lo.y = pkh2(a.z - hifh(a.z), a.w - hifh(a.w));
    lo.z = pkh2(b.x - hifh(b.x), b.y - hifh(b.y));
    lo.w = pkh2(b.z - hifh(b.z), b.w - hifh(b.w));
}
__device__ __forceinline__ uint4 cvt8_p(float4 a, float4 b) {
    uint4 h;
    h.x = pkh2(a.x, a.y); h.y = pkh2(a.z, a.w);
    h.z = pkh2(b.x, b.y); h.w = pkh2(b.z, b.w);
    return h;
}

// =================== mma.sync split-fp16 GEMM (2-pass) ======================
// C[M,N] = A[M,P] @ BT[N,P]^T (+bias)(+res)(gelu). A fp32 (hi/lo split in
// kernel), BT fp16 K-major (pre-converted). fp32 accumulate.
// CTA tile 128x128, K-slab 32, 16 warps (4x4), warp tile 32x32.
#define KS 32
#define BMT 128
#define BNT 128
#define AHI 0
#define ALO 8192
#define BHI 16384
#define STG 24576
#define GEMM_SMEM (2*STG)

__global__ __launch_bounds__(512, 1) void mgemm_k(
    const float* __restrict__ A, const __half* __restrict__ BT,
    const float* __restrict__ bias, const float* res, float* __restrict__ C,
    int M, int P, int N, int act, int rowseg, long long segstride)
{
    extern __shared__ char smemb[];
    const uint32_t sb = smem_u32(smemb);
    const int tid = threadIdx.x, lane = tid & 31, wid = tid >> 5;
    const int wr = wid >> 2, wc = wid & 3;
    const int row0 = blockIdx.y * BMT, col0 = blockIdx.x * BNT;

    const int g = lane >> 3, ri = lane & 7;
    uint32_t aoff[2]; uint32_t asw[2];
    #pragma unroll
    for (int f = 0; f < 2; f++) {
        int m = wr*32 + f*16 + (g & 1)*8 + ri;
        aoff[f] = m * 64; asw[f] = (m >> 1) & 3;
    }
    const uint32_t qa = g >> 1;
    uint32_t boff[2]; uint32_t bsw[2];
    #pragma unroll
    for (int p = 0; p < 2; p++) {
        int n = wc*32 + p*16 + (g >> 1)*8 + ri;
        boff[p] = n * 64; bsw[p] = (n >> 1) & 3;
    }
    const uint32_t qb = g & 1;

    float acc[2][4][4];
    #pragma unroll
    for (int f = 0; f < 2; f++)
        #pragma unroll
        for (int j = 0; j < 4; j++)
            #pragma unroll
            for (int e = 0; e < 4; e++) acc[f][j][e] = 0.f;

    const int ra = tid >> 2, qc = tid & 3;
    const uint32_t soff = ra*64 + (((uint32_t)qc ^ ((ra>>1)&3)) << 4);
    const float*  asrc = A  + (long)(row0 + ra) * P + qc*8;
    const __half* bsrc = BT + (long)(col0 + ra) * P + qc*8;
    const int NS = P / KS;

    float4 sA0, sA1; uint4 sB;
    sA0 = *(const float4*)asrc;
    sA1 = *(const float4*)(asrc + 4);
    sB  = *(const uint4*)bsrc;
    {
        uint4 hi, lo; cvt8_hl(sA0, sA1, hi, lo);
        sts128(sb + AHI + soff, hi);
        sts128(sb + ALO + soff, lo);
        sts128(sb + BHI + soff, sB);
    }
    __syncthreads();

    for (int s = 0; s < NS; s++) {
        const uint32_t cb = sb + (s & 1) * STG;
        if (s + 1 < NS) {
            const int k0 = (s + 1) * KS;
            sA0 = *(const float4*)(asrc + k0);
            sA1 = *(const float4*)(asrc + k0 + 4);
            sB  = *(const uint4*)(bsrc + k0);
        }

        #pragma unroll
        for (int kst = 0; kst < 2; kst++) {
            uint32_t ah[2][4], al[2][4], bh[2][4];
            #pragma unroll
            for (int f = 0; f < 2; f++) {
                uint32_t off = aoff[f] + ((((uint32_t)(kst*2) + qa) ^ asw[f]) << 4);
                ldsm4(ah[f], cb + AHI + off);
                ldsm4(al[f], cb + ALO + off);
            }
            #pragma unroll
            for (int p = 0; p < 2; p++) {
                uint32_t off = boff[p] + ((((uint32_t)(kst*2) + qb) ^ bsw[p]) << 4);
                ldsm4(bh[p], cb + BHI + off);
            }
            #pragma unroll
            for (int f = 0; f < 2; f++)
                #pragma unroll
                for (int j = 0; j < 4; j++)
                    mma16816(acc[f][j], ah[f], bh[j>>1][(j&1)*2], bh[j>>1][(j&1)*2+1]);
            #pragma unroll
            for (int f = 0; f < 2; f++)
                #pragma unroll
                for (int j = 0; j < 4; j++)
                    mma16816(acc[f][j], al[f], bh[j>>1][(j&1)*2], bh[j>>1][(j&1)*2+1]);
        }

        if (s + 1 < NS) {
            const uint32_t nb = sb + ((s + 1) & 1) * STG;
            uint4 hi, lo; cvt8_hl(sA0, sA1, hi, lo);
            sts128(nb + AHI + soff, hi);
            sts128(nb + ALO + soff, lo);
            sts128(nb + BHI + soff, sB);
        }
        __syncthreads();
    }

    #pragma unroll
    for (int f = 0; f < 2; f++) {
        #pragma unroll
        for (int j = 0; j < 4; j++) {
            int r = row0 + wr*32 + f*16 + (lane >> 2);
            int c = col0 + wc*32 + j*8 + (lane & 3)*2;
            #pragma unroll
            for (int half = 0; half < 2; half++) {
                int rr = r + half*8;
                float x0 = acc[f][j][half*2], x1 = acc[f][j][half*2+1];
                if (bias) { x0 += bias[c]; x1 += bias[c+1]; }
                if (res)  {
                    const float* rp = res + (long)rr*N + c;
                    x0 += rp[0]; x1 += rp[1];
                }
                if (act == 1) {
                    x0 = 0.5f*x0*(1.f + erff(x0*0.70710678118654752f));
                    x1 = 0.5f*x1*(1.f + erff(x1*0.70710678118654752f));
                }
                long ob = (long)(rr / rowseg) * segstride + (long)(rr % rowseg) * N + c;
                *(float2*)(C + ob) = make_float2(x0, x1);
            }
        }
    }
}

// =================== tensor-core flash attention (fp16 mma) =================
// CTA: 64 queries (4 warps x 16q), kv tiles of 64. Q/K in 3 swizzled k-slabs
// (fp16), V natural [kv][96] fp16 with 208B row pitch (conflict-free
// ldmatrix.trans). Online softmax on fragments; P stays in registers.
#define AT_QS 0
#define AT_KS 12288
#define AT_VS 24576
#define AT_SMEM (24576 + 64*208)

__global__ __launch_bounds__(128, 1) void attn3_k(
    const float* __restrict__ q, const float* __restrict__ kcat,
    const float* __restrict__ vcat, float* __restrict__ out)
{
    extern __shared__ char smemb[];
    const uint32_t sb = smem_u32(smemb);
    const int qt = blockIdx.x, h = blockIdx.y, b = blockIdx.z;
    const int tid = threadIdx.x, lane = tid & 31, wid = tid >> 5;
    const int g = lane >> 3, ri = lane & 7;
    const float scale = 0.10206207261596575f; // 96^-0.5

    // ---- stage Q tile (64 x 96) pre-scaled fp16, 3 k-slabs, swizzled ----
    for (int t = tid; t < 768; t += 128) {
        int row = t / 12, c = t % 12, slab = c >> 2, cc = c & 3;
        const float* src = q + ((long)(b*NN + qt*64 + row)*HH + h*DH + slab*32 + cc*8);
        float4 v0 = *(const float4*)src, v1 = *(const float4*)(src + 4);
        uint4 hv;
        hv.x = pkh2(v0.x*scale, v0.y*scale); hv.y = pkh2(v0.z*scale, v0.w*scale);
        hv.z = pkh2(v1.x*scale, v1.y*scale); hv.w = pkh2(v1.z*scale, v1.w*scale);
        uint32_t off = slab*4096 + row*64 + (((uint32_t)cc ^ ((row>>1)&3)) << 4);
        sts128(sb + AT_QS + off, hv);
    }
    __syncthreads();

    // Q fragments for this warp's 16 rows: 6 k16 fragments
    uint32_t qf[6][4];
    {
        int mrow = wid*16 + (g & 1)*8 + ri;
        uint32_t qa = g >> 1, asw = (mrow >> 1) & 3;
        #pragma unroll
        for (int k16 = 0; k16 < 6; k16++) {
            int slab = k16 >> 1, kst = k16 & 1;
            uint32_t off = slab*4096 + mrow*64
                         + ((((uint32_t)(kst*2) + qa) ^ asw) << 4);
            ldsm4(qf[k16], sb + AT_QS + off);
        }
    }

    float O[12][4];
    #pragma unroll
    for (int o = 0; o < 12; o++)
        #pragma unroll
        for (int e = 0; e < 4; e++) O[o][e] = 0.f;
    float m0 = -1e30f, m1 = -1e30f, l0 = 0.f, l1 = 0.f;

    const int nrow = (g >> 1)*8 + ri;      // B-row within its 16-group
    const uint32_t qb = g & 1;
    const int vr = (lane & 7) + ((lane >> 3) & 1)*8;
    const int vc16 = (lane >> 4)*16;
    const int ntiles = SS/64 + qt + 1;     // 9 + qt

    for (int jt = 0; jt < ntiles; jt++) {
        __syncthreads();
        // stage K (swizzled slabs) + V (natural, 208B pitch) for this tile
        for (int t = tid; t < 768; t += 128) {
            int row = t / 12, c = t % 12;
            long jr = ((long)b*KVLEN + jt*64 + row)*HH + h*DH;
            int slab = c >> 2, cc = c & 3;
            const float* ks = kcat + jr + slab*32 + cc*8;
            uint4 hk = cvt8_p(*(const float4*)ks, *(const float4*)(ks + 4));
            uint32_t koff = slab*4096 + row*64 + (((uint32_t)cc ^ ((row>>1)&3)) << 4);
            sts128(sb + AT_KS + koff, hk);
            const float* vs = vcat + jr + c*8;
            uint4 hv = cvt8_p(*(const float4*)vs, *(const float4*)(vs + 4));
            sts128(sb + AT_VS + row*208 + c*16, hv);
        }
        __syncthreads();

        // S = Qs @ K^T : 16q x 64kv (8 n8 accum tiles)
        float S[8][4];
        #pragma unroll
        for (int t8 = 0; t8 < 8; t8++)
            #pragma unroll
            for (int e = 0; e < 4; e++) S[t8][e] = 0.f;

        #pragma unroll
        for (int k16 = 0; k16 < 6; k16++) {
            int slab = k16 >> 1, kst = k16 & 1;
            #pragma unroll
            for (int p = 0; p < 4; p++) {
                int brow = p*16 + nrow;
                uint32_t off = slab*4096 + brow*64
                             + ((((uint32_t)(kst*2) + qb) ^ ((brow>>1)&3)) << 4);
                uint32_t bh[4];
                ldsm4(bh, sb + AT_KS + off);
                mma16816(S[2*p],     qf[k16], bh[0], bh[1]);
                mma16816(S[2*p + 1], qf[k16], bh[2], bh[3]);
            }
        }

        // causal mask: only on the diagonal (last) tile
        if (jt == ntiles - 1) {
            int r0 = wid*16 + (lane >> 2);
            #pragma unroll
            for (int t8 = 0; t8 < 8; t8++)
                #pragma unroll
                for (int e = 0; e < 2; e++) {
                    int col = t8*8 + 2*(lane & 3) + e;
                    if (col > r0)     S[t8][e]     = -1e30f;
                    if (col > r0 + 8) S[t8][2 + e] = -1e30f;
                }
        }

        // online softmax (row stats shared across each lane-quad)
        float mx0 = -1e30f, mx1 = -1e30f;
        #pragma unroll
        for (int t8 = 0; t8 < 8; t8++) {
            mx0 = fmaxf(mx0, fmaxf(S[t8][0], S[t8][1]));
            mx1 = fmaxf(mx1, fmaxf(S[t8][2], S[t8][3]));
        }
        mx0 = fmaxf(mx0, __shfl_xor_sync(0xffffffffu, mx0, 1));
        mx0 = fmaxf(mx0, __shfl_xor_sync(0xffffffffu, mx0, 2));
        mx1 = fmaxf(mx1, __shfl_xor_sync(0xffffffffu, mx1, 1));
        mx1 = fmaxf(mx1, __shfl_xor_sync(0xffffffffu, mx1, 2));
        float mn0 = fmaxf(m0, mx0), mn1 = fmaxf(m1, mx1);
        float f0 = __expf(m0 - mn0), f1 = __expf(m1 - mn1);
        float s0 = 0.f, s1 = 0.f;
        #pragma unroll
        for (int t8 = 0; t8 < 8; t8++) {
            S[t8][0] = __expf(S[t8][0] - mn0); s0 += S[t8][0];
            S[t8][1] = __expf(S[t8][1] - mn0); s0 += S[t8][1];
            S[t8][2] = __expf(S[t8][2] - mn1); s1 += S[t8][2];
            S[t8][3] = __expf(S[t8][3] - mn1); s1 += S[t8][3];
        }
        s0 += __shfl_xor_sync(0xffffffffu, s0, 1);
        s0 += __shfl_xor_sync(0xffffffffu, s0, 2);
        s1 += __shfl_xor_sync(0xffffffffu, s1, 1);
        s1 += __shfl_xor_sync(0xffffffffu, s1, 2);
        l0 = l0*f0 + s0; l1 = l1*f1 + s1;
        m0 = mn0; m1 = mn1;
        #pragma unroll
        for (int o = 0; o < 12; o++) {
            O[o][0] *= f0; O[o][1] *= f0;
            O[o][2] *= f1; O[o][3] *= f1;
        }

        // P fragments (register repack) then O += P @ V
        uint32_t pa[4][4];
        #pragma unroll
        for (int j16 = 0; j16 < 4; j16++) {
            pa[j16][0] = pkh2(S[2*j16][0],     S[2*j16][1]);
            pa[j16][1] = pkh2(S[2*j16][2],     S[2*j16][3]);
            pa[j16][2] = pkh2(S[2*j16 + 1][0], S[2*j16 + 1][1]);
            pa[j16][3] = pkh2(S[2*j16 + 1][2], S[2*j16 + 1][3]);
        }
        #pragma unroll
        for (int j16 = 0; j16 < 4; j16++) {
            #pragma unroll
            for (int v16 = 0; v16 < 6; v16++) {
                uint32_t bv[4];
                ldsm4t(bv, sb + AT_VS + (j16*16 + vr)*208 + v16*32 + vc16);
                mma16816(O[2*v16],     pa[j16], bv[0], bv[1]);
                mma16816(O[2*v16 + 1], pa[j16], bv[2], bv[3]);
            }
        }
    }

    // normalize + write out (fp32)
    float i0 = 1.f / l0, i1 = 1.f / l1;
    long rbase = (long)(b*NN + qt*64 + wid*16 + (lane >> 2))*HH + h*DH + 2*(lane & 3);
    #pragma unroll
    for (int t8 = 0; t8 < 12; t8++) {
        *(float2*)(out + rbase + t8*8) = make_float2(O[t8][0]*i0, O[t8][1]*i0);
        *(float2*)(out + rbase + 8*HH + t8*8) = make_float2(O[t8][2]*i1, O[t8][3]*i1);
    }
}

// ---------------- weight transpose+fp16: W[l][768][C] -> WT[l][C][768] ------
__global__ void transpose_wh_k(const float* __restrict__ W, __half* __restrict__ WT,
                               int C) {
    __shared__ float tile[32][33];
    int bx = blockIdx.x, by = blockIdx.y, z = blockIdx.z;
    int tx = threadIdx.x, ty = threadIdx.y;
    const float* src = W + (long)z * HH * C;
    __half* dst = WT + (long)z * C * HH;
    #pragma unroll
    for (int j = 0; j < 32; j += 8)
        tile[ty + j][tx] = src[(long)(by * 32 + ty + j) * C + bx * 32 + tx];
    __syncthreads();
    #pragma unroll
    for (int j = 0; j < 32; j += 8)
        dst[(long)(bx * 32 + ty + j) * HH + by * 32 + tx] =
            __float2half_rn(tile[tx][ty + j]);
}

// ---------------- fp32 -> fp16 elementwise ----------------------------------
__global__ void cvt_half_k(const float* __restrict__ E, __half* __restrict__ O,
                           long n) {
    long i = (long)blockIdx.x * blockDim.x + threadIdx.x;
    if (i < n) O[i] = __float2half_rn(E[i]);
}

// ---------------- embedding gather + scale ----------------------------------
__global__ void embed_k(const int* __restrict__ ids, const float* __restrict__ E,
                        float* __restrict__ hid) {
    long idx = (long)blockIdx.x * blockDim.x + threadIdx.x;
    if (idx >= (long)MROWS*HH) return;
    int col = (int)(idx % HH);
    long row = idx / HH;
    hid[idx] = E[(long)ids[row]*HH + col] * 27.712812921102035f; // sqrt(768)
}

// ---------------- RMSNorm (GemmaRMSNorm) ------------------------------------
__global__ __launch_bounds__(256) void rmsnorm_k(const float* __restrict__ x,
                                                 const float* __restrict__ w,
                                                 float* __restrict__ y) {
    int row = blockIdx.x;
    const float* xr = x + (long)row*HH;
    float s = 0.f;
    for (int c = threadIdx.x; c < HH; c += 256) { float v = xr[c]; s += v*v; }
    __shared__ float red[8];
    #pragma unroll
    for (int o = 16; o; o >>= 1) s += __shfl_xor_sync(~0u, s, o);
    if ((threadIdx.x & 31) == 0) red[threadIdx.x >> 5] = s;
    __syncthreads();
    if (threadIdx.x < 8) {
        float t = red[threadIdx.x];
        #pragma unroll
        for (int o = 4; o; o >>= 1) t += __shfl_xor_sync(0xffu, t, o);
        if (threadIdx.x == 0) red[0] = t;
    }
    __syncthreads();
    float inv = rsqrtf(red[0] / (float)HH + 1e-6f);
    for (int c = threadIdx.x; c < HH; c += 256)
        y[(long)row*HH + c] = xr[c] * inv * (1.f + w[c]);
}

// ---------------- RoPE cos/sin table ----------------------------------------
__global__ void rope_tab_k(float* __restrict__ ct, float* __restrict__ st) {
    int idx = blockIdx.x * blockDim.x + threadIdx.x;
    if (idx >= NN*DH) return;
    int n = idx / DH, dd = idx % DH;
    int t = (dd < DH/2) ? dd : dd - DH/2;
    float invf = __powf(10000.f, -((float)(2*t) / (float)DH));
    float fd = (float)n * invf;
    ct[idx] = cosf(fd);
    st[idx] = sinf(fd);
}

// ---------------- RoPE + q/k/v split-scatter --------------------------------
__global__ void rope_split_k(const float* __restrict__ qkv, float* __restrict__ qb,
                             float* __restrict__ kcat, float* __restrict__ vcat,
                             const float* __restrict__ ct, const float* __restrict__ st) {
    long idx = (long)blockIdx.x * blockDim.x + threadIdx.x;
    if (idx >= (long)MROWS*HH) return;
    int col = (int)(idx % HH);
    long row = idx / HH;
    int n = (int)(row % NN);
    int b = (int)(row / NN);
    int dd = col % DH;
    const float* base = qkv + row*(3*HH);
    float qv = base[col], kv = base[HH + col], vv = base[2*HH + col];
    float c = ct[n*DH + dd], s = st[n*DH + dd];
    float qrot = (dd < DH/2) ? -base[col + DH/2]      : base[col - DH/2];
    float krot = (dd < DH/2) ? -base[HH + col + DH/2] : base[HH + col - DH/2];
    qb[row*HH + col] = qv*c + qrot*s;
    long outk = ((long)b*KVLEN + SS + n)*HH + col;
    kcat[outk] = kv*c + krot*s;
    vcat[outk] = vv;
}

// ---------------- host launcher ---------------------------------------------
static void mg(const float* A, const __half* BT, const float* bias,
               const float* res, float* C, int M, int P, int N,
               int act, int rowseg, long long segstride) {
    dim3 grid(N / BNT, M / BMT);
    mgemm_k<<<grid, 512, GEMM_SMEM>>>(A, BT, bias, res, C, M, P, N,
                                      act, rowseg, segstride);
}

extern "C" void kernel_launch(void* const* d_in, const int* in_sizes, int n_in,
                              void* d_out, int out_size) {
    const int*   ids    = (const int*)  d_in[0];
    const float* vkey   = (const float*)d_in[1];   // [L,B,S,H]
    const float* vval   = (const float*)d_in[2];
    const float* embedW = (const float*)d_in[3];   // [V,H]
    const float* n1w    = (const float*)d_in[4];
    const float* n2w    = (const float*)d_in[5];
    const float* qkvW   = (const float*)d_in[6];   // [L,H,3H]
    const float* qkvB   = (const float*)d_in[7];
    const float* skvW   = (const float*)d_in[8];
    const float* skvB   = (const float*)d_in[9];
    const float* outW   = (const float*)d_in[10];
    const float* outB   = (const float*)d_in[11];
    const float* f1W    = (const float*)d_in[12];
    const float* f1B    = (const float*)d_in[13];
    const float* f2W    = (const float*)d_in[14];
    const float* f2B    = (const float*)d_in[15];
    float* logits = (float*)d_out;

    float *hid, *x, *qkv, *q, *kc, *vc, *attn, *ffn, *ct, *st;
    __half *qkvTh, *skvTh, *outTh, *f1Th, *f2Th, *embh;
    cudaGetSymbolAddress((void**)&hid,   g_hidden);
    cudaGetSymbolAddress((void**)&x,     g_x);
    cudaGetSymbolAddress((void**)&qkv,   g_qkv);
    cudaGetSymbolAddress((void**)&q,     g_q);
    cudaGetSymbolAddress((void**)&kc,    g_kcat);
    cudaGetSymbolAddress((void**)&vc,    g_vcat);
    cudaGetSymbolAddress((void**)&attn,  g_attn);
    cudaGetSymbolAddress((void**)&ffn,   g_ffn);
    cudaGetSymbolAddress((void**)&ct,    g_cos);
    cudaGetSymbolAddress((void**)&st,    g_sin);
    cudaGetSymbolAddress((void**)&qkvTh, g_qkvTh);
    cudaGetSymbolAddress((void**)&skvTh, g_skvTh);
    cudaGetSymbolAddress((void**)&outTh, g_outTh);
    cudaGetSymbolAddress((void**)&f1Th,  g_f1Th);
    cudaGetSymbolAddress((void**)&f2Th,  g_f2Th);
    cudaGetSymbolAddress((void**)&embh,  g_embedh);

    cudaFuncSetAttribute(mgemm_k, cudaFuncAttributeMaxDynamicSharedMemorySize, GEMM_SMEM);
    cudaFuncSetAttribute(attn3_k, cudaFuncAttributeMaxDynamicSharedMemorySize, AT_SMEM);

    // per-call weight transposes into K-major fp16 [N,K]
    transpose_wh_k<<<dim3(3*HH/32, HH/32, LN), dim3(32, 8)>>>(qkvW, qkvTh, 3*HH);
    transpose_wh_k<<<dim3(HH/32, HH/32, LN), dim3(32, 8)>>>(skvW, skvTh, HH);
    transpose_wh_k<<<dim3(HH/32, HH/32, LN), dim3(32, 8)>>>(outW, outTh, HH);
    transpose_wh_k<<<dim3(HH/32, HH/32, LN), dim3(32, 8)>>>(f1W,  f1Th,  HH);
    transpose_wh_k<<<dim3(HH/32, HH/32, LN), dim3(32, 8)>>>(f2W,  f2Th,  HH);
    // embed fp16 copy for lm_head (already K-major [V,H])
    {
        long n = (long)VV * HH;
        cvt_half_k<<<(int)((n + 255) / 256), 256>>>(embedW, embh, n);
    }

    const int elemBlocks = (MROWS*HH + 255) / 256;
    embed_k<<<elemBlocks, 256>>>(ids, embedW, hid);
    rope_tab_k<<<(NN*DH + 255)/256, 256>>>(ct, st);

    const long HW  = (long)HH * HH;
    const long BSH = (long)BB * SS * HH;

    for (int l = 0; l < LN; l++) {
        rmsnorm_k<<<MROWS, 256>>>(hid, n1w + l*HH, x);
        mg(x, qkvTh + (long)l*3*HW, qkvB + l*3*HH, nullptr, qkv,
           MROWS, HH, 3*HH, 0, MROWS, 0);
        rope_split_k<<<elemBlocks, 256>>>(qkv, q, kc, vc, ct, st);
        mg(vkey + (long)l*BSH, skvTh + l*HW, skvB + l*HH, nullptr, kc,
           MROWS, HH, HH, 0, SS, (long long)KVLEN*HH);
        mg(vval + (long)l*BSH, skvTh + l*HW, skvB + l*HH, nullptr, vc,
           MROWS, HH, HH, 0, SS, (long long)KVLEN*HH);
        attn3_k<<<dim3(NN/64, NH, BB), 128, AT_SMEM>>>(q, kc, vc, attn);
        mg(attn, outTh + l*HW, outB + l*HH, hid, hid,
           MROWS, HH, HH, 0, MROWS, 0);
        rmsnorm_k<<<MROWS, 256>>>(hid, n2w + l*HH, x);
        mg(x, f1Th + l*HW, f1B + l*HH, nullptr, ffn,
           MROWS, HH, HH, 1, MROWS, 0);
        mg(ffn, f2Th + l*HW, f2B + l*HH, hid, hid,
           MROWS, HH, HH, 0, MROWS, 0);
    }

    // tied lm_head: logits = hidden @ embed^T ; embedh is [N=V, K=H] fp16
    mg(hid, embh, nullptr, nullptr, logits, MROWS, HH, VV, 0, MROWS, 0);
}